// round 12
// baseline (speedup 1.0000x reference)
#include <cuda_runtime.h>
#include <cuda_fp16.h>
#include <cstdint>
#include <math.h>

// ---------------- problem dims ----------------
#define BATCH 2048
#define TLEN  80
#define EDIM  100
#define NWORDS 35000
#define UNITS 512
#define KC    64               // K chunk (64 fp16 = 128 B row)
#define BM    128
#define BN    64
#define NCTA  128
#define GRPSZ 8

// ---------------- static device scratch ----------------
__device__ __half g_H[2][BATCH * UNITS];          // hidden state, fp16
__device__ __half g_Whh_h[UNITS * UNITS];         // W_hh single fp16 plane, [n][k]
__device__ __half g_WX_h[UNITS * 128];            // W_xh hi plane, [n][k pad 128]
__device__ __half g_WX_l[UNITS * 128];
__device__ float  g_EP[(size_t)NWORDS * UNITS];   // emb @ W_xh + b_h  (fp32)
__device__ unsigned g_flag[NCTA * 32];            // per (grp,col) flags, 128B stride

// ---------------- PTX helpers ----------------
__device__ __forceinline__ uint32_t smem_to_u32(const void* p) {
    uint32_t a;
    asm("{ .reg .u64 t; cvta.to.shared.u64 t, %1; cvt.u32.u64 %0, t; }" : "=r"(a) : "l"(p));
    return a;
}
__device__ __forceinline__ float tanh_fast(float x) {
    float r;
    asm("tanh.approx.f32 %0, %1;" : "=f"(r) : "f"(x));
    return r;
}
#define CP16(dst, src) \
    asm volatile("cp.async.cg.shared.global [%0], [%1], 16;" :: "r"(dst), "l"(src))
#define CP_COMMIT() asm volatile("cp.async.commit_group;" ::: "memory")
#define CP_WAIT(n)  asm volatile("cp.async.wait_group %0;" :: "n"(n) : "memory")

#define LDSM_X4(r0, r1, r2, r3, addr) \
    asm volatile("ldmatrix.sync.aligned.m8n8.x4.shared.b16 {%0,%1,%2,%3}, [%4];" \
                 : "=r"(r0), "=r"(r1), "=r"(r2), "=r"(r3) : "r"(addr))

#define MMAF16(d, a0, a1, a2, a3, b0, b1) \
    asm volatile("mma.sync.aligned.m16n8k16.row.col.f32.f16.f16.f32 " \
                 "{%0,%1,%2,%3}, {%4,%5,%6,%7}, {%8,%9}, {%0,%1,%2,%3};" \
                 : "+f"((d)[0]), "+f"((d)[1]), "+f"((d)[2]), "+f"((d)[3]) \
                 : "r"(a0), "r"(a1), "r"(a2), "r"(a3), "r"(b0), "r"(b1))

#define SWZ(bo) ((bo) ^ (((bo) >> 3) & 0x70))

#define BAR_CTA()  asm volatile("barrier.sync 0;" ::: "memory")
#define BAR_G1()   asm volatile("barrier.sync 2, 256;" ::: "memory")

// ---------------- SMEM layouts ----------------
// main: B resident 8 chunks x 8KB = 64KB; A 8 bufs x 16KB = 128KB (g0: 0-3, g1: 4-7)
// stage (g1 partial acc + ep, 128 x 72 fp32 = 36KB) overlays bufs 4..6 (after BAR_G1).
#define B_RES(c)     ((c) * 8192)
#define A_OFF(buf)   (65536 + (buf) * 16384)
#define STAGE_OFF    A_OFF(4)
#define STG_STRIDE   72
#define SMEM_MAIN    (65536 + 8 * 16384)           // 196608
// proj: A fp16 2 chunks x 16KB = 32KB; B 2 planes x 2 chunks x 8KB = 32KB
#define PA(ch)       ((ch) * 16384)
#define PB(p, ch)    (32768 + ((p) * 2 + (ch)) * 8192)
#define SMEM_PROJ    65536

// ---------------- prep kernels ----------------
__global__ void build_whh_kernel(const float* __restrict__ Whh) {
    int i = blockIdx.x * blockDim.x + threadIdx.x;
    if (i >= UNITS * UNITS) return;
    int n = i / UNITS;
    int k = i - n * UNITS;
    g_Whh_h[i] = __float2half(Whh[(size_t)k * UNITS + n]);
}

__global__ void build_wx_kernel(const float* __restrict__ Wxh) {
    int i = blockIdx.x * blockDim.x + threadIdx.x;
    if (i >= UNITS * 128) return;
    int n = i >> 7;
    int k = i & 127;
    float v = (k < EDIM) ? Wxh[(size_t)k * UNITS + n] : 0.0f;
    __half hi = __float2half(v);
    g_WX_h[i] = hi;
    g_WX_l[i] = __float2half(v - __half2float(hi));
}

__global__ void init_h_kernel() {
    int i = blockIdx.x * blockDim.x + threadIdx.x;
    if (i < NCTA * 32) g_flag[i] = 0u;
    if (i >= BATCH * UNITS) return;
    g_H[0][i] = __float2half(0.0f);
}

// ---------------- table projection: g_EP = emb @ W_xh + b_h (hi/lo, one-shot) ----
__global__ __launch_bounds__(256, 2)
void proj_gemm(const float* __restrict__ emb, const float* __restrict__ bh) {
    extern __shared__ char smem[];
    const uint32_t su = smem_to_u32(smem);
    const int tid = threadIdx.x, wid = tid >> 5, lane = tid & 31;
    const int col0 = blockIdx.x * BN;
    const int r0   = blockIdx.y * BM;

    // zero A planes (pads k in [100,128) and rows >= NWORDS)
    {
        uint4 z = make_uint4(0, 0, 0, 0);
#pragma unroll
        for (int i = 0; i < 8; i++)
            *reinterpret_cast<uint4*>(smem + tid * 16 + i * 4096) = z;
    }
    // B planes via cp.async (disjoint region)
    {
#pragma unroll
        for (int i = 0; i < 8; i++) {
            int u = tid + i * 256;
            int p  = u >> 10;
            int rem = u & 1023;
            int ch = rem >> 9;
            int r  = (rem >> 3) & 63;
            int s  = rem & 7;
            uint32_t so = SWZ((uint32_t)(r * 128 + s * 16));
            const __half* wsrc = (p == 0 ? g_WX_h : g_WX_l) + (size_t)(col0 + r) * 128 + ch * 64;
            CP16(su + PB(p, ch) + so, (const char*)wsrc + s * 16);
        }
    }
    CP_COMMIT();
    __syncthreads();   // zero-fill visible before gather overwrites

    // vectorized A staging: 2 threads per row, float4 loads, half2 stores
    {
        const int row = tid >> 1, sub = tid & 1;
        const int gr = r0 + row;
        if (gr < NWORDS) {
            const float4* src = reinterpret_cast<const float4*>(emb + (size_t)gr * EDIM);
#pragma unroll
            for (int f4 = sub; f4 < 25; f4 += 2) {
                float4 v = __ldg(src + f4);
                int k = f4 * 4;
                int ch = k >> 6, kk = k & 63;
                uint32_t so = SWZ((uint32_t)(row * 128 + kk * 2));
                __half2 h0; h0.x = __float2half(v.x); h0.y = __float2half(v.y);
                __half2 h1; h1.x = __float2half(v.z); h1.y = __float2half(v.w);
                *reinterpret_cast<__half2*>(smem + PA(ch) + so)     = h0;
                *reinterpret_cast<__half2*>(smem + PA(ch) + so + 4) = h1;
            }
        }
    }
    CP_WAIT(0);
    __syncthreads();

    const int m_base = (wid & 3) * 32;
    const int n_base = (wid >> 2) * 32;
    const int a_row = lane & 15, a_kh = (lane >> 4) * 16;
    const int b_row = ((lane >> 4) << 3) + (lane & 7), b_kh = ((lane >> 3) & 1) * 16;
    const int lg = lane >> 2, tig = lane & 3;

    float acc[2][4][4];
#pragma unroll
    for (int mt = 0; mt < 2; mt++)
#pragma unroll
        for (int nt = 0; nt < 4; nt++)
#pragma unroll
            for (int q = 0; q < 4; q++) acc[mt][nt][q] = 0.0f;

#pragma unroll
    for (int ks = 0; ks < 7; ks++) {
        const int ch = ks >> 2;
        const int kb = (ks & 3) * 32;
        uint32_t A[2][4], Bh[4][2], Bl[4][2];
#pragma unroll
        for (int mt = 0; mt < 2; mt++) {
            uint32_t bo = SWZ((uint32_t)((m_base + mt * 16 + a_row) * 128 + kb + a_kh));
            LDSM_X4(A[mt][0], A[mt][1], A[mt][2], A[mt][3], su + PA(ch) + bo);
        }
#pragma unroll
        for (int np = 0; np < 2; np++) {
            uint32_t bo = SWZ((uint32_t)((n_base + np * 16 + b_row) * 128 + kb + b_kh));
            LDSM_X4(Bh[np * 2][0], Bh[np * 2][1], Bh[np * 2 + 1][0], Bh[np * 2 + 1][1],
                    su + PB(0, ch) + bo);
            LDSM_X4(Bl[np * 2][0], Bl[np * 2][1], Bl[np * 2 + 1][0], Bl[np * 2 + 1][1],
                    su + PB(1, ch) + bo);
        }
#pragma unroll
        for (int mt = 0; mt < 2; mt++)
#pragma unroll
            for (int nt = 0; nt < 4; nt++) {
                MMAF16(acc[mt][nt], A[mt][0], A[mt][1], A[mt][2], A[mt][3],
                       Bh[nt][0], Bh[nt][1]);
                MMAF16(acc[mt][nt], A[mt][0], A[mt][1], A[mt][2], A[mt][3],
                       Bl[nt][0], Bl[nt][1]);
            }
    }

#pragma unroll
    for (int mt = 0; mt < 2; mt++)
#pragma unroll
        for (int nt = 0; nt < 4; nt++) {
            const int col = col0 + n_base + nt * 8 + tig * 2;
            const float b0 = __ldg(bh + col);
            const float b1 = __ldg(bh + col + 1);
#pragma unroll
            for (int half = 0; half < 2; half++) {
                const int row = r0 + m_base + mt * 16 + lg + half * 8;
                if (row < NWORDS) {
                    float2 v;
                    v.x = acc[mt][nt][half * 2] + b0;
                    v.y = acc[mt][nt][half * 2 + 1] + b1;
                    *reinterpret_cast<float2*>(g_EP + (size_t)row * UNITS + col) = v;
                }
            }
        }
}

// ---------------- persistent recurrence: split-K(2), per-warp A pipelines ----------------
__global__ __launch_bounds__(512, 1)
void rnn_persistent(const int* __restrict__ inputs) {
    extern __shared__ char smem[];
    const uint32_t su = smem_to_u32(smem);
    const int tid = threadIdx.x, wid = tid >> 5, lane = tid & 31;
    const int kg  = wid >> 3;                      // k-group 0/1
    const int wg  = wid & 7;
    const int bid = blockIdx.x;
    const int cidx = bid & 7;
    const int grp  = bid >> 3;
    const int col0 = cidx * BN, row0 = grp * BM;

    // resident B: W_hh single plane, 8 chunks
    {
#pragma unroll
        for (int i = 0; i < 8; i++) {
            int u = tid + i * 512;
            int rg = u >> 3, s = u & 7;
            int ch = rg >> 6, r = rg & 63;
            uint32_t so = SWZ((uint32_t)(r * 128 + s * 16));
            size_t gs = (size_t)(col0 + r) * UNITS + ch * 64;
            CP16(su + B_RES(ch) + so, (const char*)(g_Whh_h + gs) + s * 16);
        }
    }
    CP_COMMIT();
    // prefill A buffer 0 with zeros (H_0 own chunk, forwarded path)
    {
        uint4 z = make_uint4(0, 0, 0, 0);
        reinterpret_cast<uint4*>(smem + A_OFF(0))[tid]       = z;
        reinterpret_cast<uint4*>(smem + A_OFF(0))[tid + 512] = z;
    }
    CP_WAIT(0);
    __syncthreads();

    const int m_base = (wg & 3) * 32;
    const int n_base = (wg >> 2) * 32;
    const int a_row = lane & 15, a_kh = (lane >> 4) * 16;
    const int b_row = ((lane >> 4) << 3) + (lane & 7), b_kh = ((lane >> 3) & 1) * 16;
    const int lg = lane >> 2, tig = lane & 3;

    for (int t = 0; t < TLEN; t++) {
        const __half* __restrict__ Hsrc = g_H[t & 1];

        float acc[2][4][4];
#pragma unroll
        for (int mt = 0; mt < 2; mt++)
#pragma unroll
            for (int nt = 0; nt < 4; nt++)
#pragma unroll
                for (int q = 0; q < 4; q++) acc[mt][nt][q] = 0.0f;

        auto spin = [&](int kc) {
            const unsigned* fp = &g_flag[(grp * 8 + kc) * 32];
            unsigned v;
            do {
                asm volatile("ld.acquire.gpu.u32 %0, [%1];" : "=r"(v) : "l"(fp));
            } while ((int)v < t);
        };
        // per-warp: load ONLY this warp's 32 A-rows of chunk kc into buf.
        // Pair-warp writes identical bytes to the same addresses (benign).
        auto load_A = [&](int kc, int buf) {
            const __half* sh = Hsrc + (size_t)(row0 + m_base) * UNITS + kc * KC;
#pragma unroll
            for (int i = 0; i < 8; i++) {
                int u = lane + i * 32;           // 0..255
                int r = u >> 3, s = u & 7;       // r 0..31
                uint32_t so = SWZ((uint32_t)((m_base + r) * 128 + s * 16));
                CP16(su + A_OFF(buf) + so, (const char*)(sh + (size_t)r * UNITS) + s * 16);
            }
            CP_COMMIT();
        };

#define PROC_CHUNK(abuf, kc) do {                                             \
            const uint32_t ah_ = su + A_OFF(abuf);                            \
            const uint32_t bh_ = su + B_RES(kc);                              \
            _Pragma("unroll")                                                 \
            for (int ks_ = 0; ks_ < 4; ks_++) {                               \
                const int kb_ = ks_ * 32;                                     \
                uint32_t Af_[2][4], Bh_[4][2];                                \
                _Pragma("unroll")                                             \
                for (int mt_ = 0; mt_ < 2; mt_++) {                           \
                    uint32_t bo = SWZ((uint32_t)((m_base + mt_ * 16 + a_row)  \
                                                 * 128 + kb_ + a_kh));        \
                    LDSM_X4(Af_[mt_][0], Af_[mt_][1], Af_[mt_][2],            \
                            Af_[mt_][3], ah_ + bo);                           \
                }                                                             \
                _Pragma("unroll")                                             \
                for (int np_ = 0; np_ < 2; np_++) {                           \
                    uint32_t bo = SWZ((uint32_t)((n_base + np_ * 16 + b_row)  \
                                                 * 128 + kb_ + b_kh));        \
                    LDSM_X4(Bh_[np_ * 2][0], Bh_[np_ * 2][1],                 \
                            Bh_[np_ * 2 + 1][0], Bh_[np_ * 2 + 1][1],         \
                            bh_ + bo);                                        \
                }                                                             \
                _Pragma("unroll")                                             \
                for (int mt_ = 0; mt_ < 2; mt_++)                             \
                    _Pragma("unroll")                                         \
                    for (int nt_ = 0; nt_ < 4; nt_++)                         \
                        MMAF16(acc[mt_][nt_], Af_[mt_][0], Af_[mt_][1],       \
                               Af_[mt_][2], Af_[mt_][3],                      \
                               Bh_[nt_][0], Bh_[nt_][1]);                     \
            }                                                                 \
        } while (0)

        if (kg == 0) {
            const int k1 = (cidx + 1) & 7, k2 = (cidx + 2) & 7, k3 = (cidx + 3) & 7;
            spin(k1); load_A(k1, 1);
            spin(k2); load_A(k2, 2);
            PROC_CHUNK(0, cidx);               // own chunk, smem-forwarded
            CP_WAIT(1);                         // k1 in (this warp's rows)
            spin(k3); load_A(k3, 3);
            PROC_CHUNK(1, k1);
            CP_WAIT(1);                         // k2 in
            PROC_CHUNK(2, k2);
            CP_WAIT(0);                         // k3 in
            PROC_CHUNK(3, k3);

            BAR_CTA();                          // #1: stage ready (pairs with g1)

            // ---- combine + tanh + store + forward ----
            __half* __restrict__ Hdst = g_H[(t + 1) & 1];
            const float* stg = reinterpret_cast<const float*>(smem + STAGE_OFF);
#pragma unroll
            for (int mt = 0; mt < 2; mt++)
#pragma unroll
                for (int nt = 0; nt < 4; nt++) {
                    const int col_l = n_base + nt * 8 + tig * 2;
                    const int col   = col0 + col_l;
#pragma unroll
                    for (int half = 0; half < 2; half++) {
                        const int row_l = m_base + mt * 16 + lg + half * 8;
                        float2 s2 = *reinterpret_cast<const float2*>(
                                        stg + row_l * STG_STRIDE + col_l);
                        float v0 = tanh_fast(acc[mt][nt][half * 2 + 0] + s2.x);
                        float v1 = tanh_fast(acc[mt][nt][half * 2 + 1] + s2.y);
                        __half2 hp;
                        hp.x = __float2half(v0);
                        hp.y = __float2half(v1);
                        *reinterpret_cast<__half2*>(
                            Hdst + (size_t)(row0 + row_l) * UNITS + col) = hp;
                        uint32_t so = SWZ((uint32_t)(row_l * 128 + col_l * 2));
                        *reinterpret_cast<__half2*>(smem + A_OFF(0) + so) = hp;
                    }
                }

            BAR_CTA();                          // #2: forwarding + stores visible
            if (tid == 0) {
                __threadfence();
                unsigned* fp = &g_flag[(grp * 8 + cidx) * 32];
                asm volatile("st.release.gpu.u32 [%0], %1;"
                             :: "l"(fp), "r"((unsigned)(t + 1)) : "memory");
            }
        } else {
            // ---- EP gather (xw + bias, fp32) — issued early, consumed at stage ----
            float ep[2][4][4];
#pragma unroll
            for (int mt = 0; mt < 2; mt++)
#pragma unroll
                for (int half = 0; half < 2; half++) {
                    const int row = row0 + m_base + mt * 16 + lg + half * 8;
                    const int idx = __ldg(inputs + (size_t)row * TLEN + t);
                    const float* eprow = g_EP + (size_t)idx * UNITS + col0;
#pragma unroll
                    for (int nt = 0; nt < 4; nt++) {
                        float2 v = __ldg(reinterpret_cast<const float2*>(
                                             eprow + n_base + nt * 8 + tig * 2));
                        ep[mt][nt][half * 2]     = v.x;
                        ep[mt][nt][half * 2 + 1] = v.y;
                    }
                }

            const int k4 = (cidx + 4) & 7, k5 = (cidx + 5) & 7;
            const int k6 = (cidx + 6) & 7, k7 = (cidx + 7) & 7;
            spin(k4); load_A(k4, 4);
            spin(k5); load_A(k5, 5);
            spin(k6); load_A(k6, 6);
            CP_WAIT(2); PROC_CHUNK(4, k4);
            spin(k7); load_A(k7, 7);
            CP_WAIT(2); PROC_CHUNK(5, k5);
            CP_WAIT(1); PROC_CHUNK(6, k6);
            CP_WAIT(0); PROC_CHUNK(7, k7);

            BAR_G1();                           // all g1 A-reads of bufs 4-6 done
                                                // before stage overlay write

            // ---- stage partial acc + ep (overlays bufs 4..6) ----
            float* stg = reinterpret_cast<float*>(smem + STAGE_OFF);
#pragma unroll
            for (int mt = 0; mt < 2; mt++)
#pragma unroll
                for (int nt = 0; nt < 4; nt++) {
                    const int col_l = n_base + nt * 8 + tig * 2;
#pragma unroll
                    for (int half = 0; half < 2; half++) {
                        const int row_l = m_base + mt * 16 + lg + half * 8;
                        float2 w;
                        w.x = acc[mt][nt][half * 2 + 0] + ep[mt][nt][half * 2 + 0];
                        w.y = acc[mt][nt][half * 2 + 1] + ep[mt][nt][half * 2 + 1];
                        *reinterpret_cast<float2*>(
                            stg + row_l * STG_STRIDE + col_l) = w;
                    }
                }
            BAR_CTA();                          // #1: stage visible to g0
            BAR_CTA();                          // #2: g0 done; bufs reusable
        }
#undef PROC_CHUNK
    }
}

// ---------------- final logits ----------------
__global__ __launch_bounds__(256)
void final_logits_kernel(const float* __restrict__ Wout,
                         const float* __restrict__ bout,
                         float* __restrict__ out) {
    const __half* __restrict__ h = g_H[0];   // TLEN = 80 even -> plane 0
    int warp = threadIdx.x >> 5;
    int lane = threadIdx.x & 31;
    int row = blockIdx.x * 8 + warp;
    if (row >= BATCH) return;
    float s = 0.0f;
#pragma unroll
    for (int j = 0; j < UNITS / 32; j++) {
        int k = lane + j * 32;
        s += __half2float(h[(size_t)row * UNITS + k]) * Wout[k];
    }
#pragma unroll
    for (int o = 16; o; o >>= 1) s += __shfl_xor_sync(0xffffffff, s, o);
    if (lane == 0) out[row] = 1.0f / (1.0f + expf(-(s + bout[0])));
}

// ---------------- launch ----------------
extern "C" void kernel_launch(void* const* d_in, const int* in_sizes, int n_in,
                              void* d_out, int out_size) {
    const int*   inputs = (const int*)  d_in[0];
    const float* emb    = (const float*)d_in[1];
    const float* Wxh    = (const float*)d_in[2];
    const float* Whh    = (const float*)d_in[3];
    const float* bh     = (const float*)d_in[4];
    const float* Wout   = (const float*)d_in[5];
    const float* bout   = (const float*)d_in[6];
    float* out = (float*)d_out;

    cudaFuncSetAttribute(rnn_persistent,
                         cudaFuncAttributeMaxDynamicSharedMemorySize, SMEM_MAIN);
    cudaFuncSetAttribute(proj_gemm,
                         cudaFuncAttributeMaxDynamicSharedMemorySize, SMEM_PROJ);

    build_whh_kernel<<<(UNITS * UNITS + 255) / 256, 256>>>(Whh);
    build_wx_kernel<<<(UNITS * 128 + 255) / 256, 256>>>(Wxh);
    init_h_kernel<<<(BATCH * UNITS + 255) / 256, 256>>>();

    dim3 gp(UNITS / BN, (NWORDS + BM - 1) / BM);   // (8, 274)
    proj_gemm<<<gp, 256, SMEM_PROJ>>>(emb, bh);

    rnn_persistent<<<NCTA, 512, SMEM_MAIN>>>(inputs);

    final_logits_kernel<<<BATCH / 8, 256>>>(Wout, bout, out);
}

// round 13
// speedup vs baseline: 1.0002x; 1.0002x over previous
#include <cuda_runtime.h>
#include <cuda_fp16.h>
#include <cstdint>
#include <math.h>

// ---------------- problem dims ----------------
#define BATCH 2048
#define TLEN  80
#define EDIM  100
#define NWORDS 35000
#define UNITS 512
#define KC    64               // K chunk (64 fp16 = 128 B row)
#define BM    128
#define BN    64
#define NCTA  128
#define GRPSZ 8

// ---------------- static device scratch ----------------
__device__ __half g_H[2][BATCH * UNITS];          // hidden state, fp16
__device__ __half g_Whh_h[UNITS * UNITS];         // W_hh single fp16 plane, [n][k]
__device__ __half g_WX_h[UNITS * 128];            // W_xh hi plane, [n][k pad 128]
__device__ __half g_WX_l[UNITS * 128];
__device__ float  g_EP[(size_t)NWORDS * UNITS];   // emb @ W_xh + b_h  (fp32)
__device__ unsigned g_flag[NCTA * 32];            // per (grp,col) flags, 128B stride

// ---------------- PTX helpers ----------------
__device__ __forceinline__ uint32_t smem_to_u32(const void* p) {
    uint32_t a;
    asm("{ .reg .u64 t; cvta.to.shared.u64 t, %1; cvt.u32.u64 %0, t; }" : "=r"(a) : "l"(p));
    return a;
}
__device__ __forceinline__ float tanh_fast(float x) {
    float r;
    asm("tanh.approx.f32 %0, %1;" : "=f"(r) : "f"(x));
    return r;
}
#define CP16(dst, src) \
    asm volatile("cp.async.cg.shared.global [%0], [%1], 16;" :: "r"(dst), "l"(src))
#define CP_COMMIT() asm volatile("cp.async.commit_group;" ::: "memory")
#define CP_WAIT(n)  asm volatile("cp.async.wait_group %0;" :: "n"(n) : "memory")

#define LDSM_X4(r0, r1, r2, r3, addr) \
    asm volatile("ldmatrix.sync.aligned.m8n8.x4.shared.b16 {%0,%1,%2,%3}, [%4];" \
                 : "=r"(r0), "=r"(r1), "=r"(r2), "=r"(r3) : "r"(addr))

#define MMAF16(d, a0, a1, a2, a3, b0, b1) \
    asm volatile("mma.sync.aligned.m16n8k16.row.col.f32.f16.f16.f32 " \
                 "{%0,%1,%2,%3}, {%4,%5,%6,%7}, {%8,%9}, {%0,%1,%2,%3};" \
                 : "+f"((d)[0]), "+f"((d)[1]), "+f"((d)[2]), "+f"((d)[3]) \
                 : "r"(a0), "r"(a1), "r"(a2), "r"(a3), "r"(b0), "r"(b1))

#define SWZ(bo) ((bo) ^ (((bo) >> 3) & 0x70))

#define BAR_CTA()  asm volatile("barrier.sync 0;" ::: "memory")
#define BAR_G1()   asm volatile("barrier.sync 1, 256;" ::: "memory")
// per-pair barrier (2 warps = 64 threads), id in [2, 10)
#define BAR_PAIR(id) asm volatile("barrier.sync %0, 64;" :: "r"(id) : "memory")

// ---------------- SMEM layouts ----------------
// main: B resident 8 chunks x 8KB = 64KB; A 8 bufs x 16KB = 128KB (g0: 0-3, g1: 4-7)
// stage (g1 partial acc + ep, 128 x 72 fp32 = 36KB) overlays bufs 4..6 (after BAR_G1).
#define B_RES(c)     ((c) * 8192)
#define A_OFF(buf)   (65536 + (buf) * 16384)
#define STAGE_OFF    A_OFF(4)
#define STG_STRIDE   72
#define SMEM_MAIN    (65536 + 8 * 16384)           // 196608
// proj: A fp16 2 chunks x 16KB = 32KB; B 2 planes x 2 chunks x 8KB = 32KB
#define PA(ch)       ((ch) * 16384)
#define PB(p, ch)    (32768 + ((p) * 2 + (ch)) * 8192)
#define SMEM_PROJ    65536

// ---------------- prep kernels ----------------
__global__ void build_whh_kernel(const float* __restrict__ Whh) {
    int i = blockIdx.x * blockDim.x + threadIdx.x;
    if (i >= UNITS * UNITS) return;
    int n = i / UNITS;
    int k = i - n * UNITS;
    g_Whh_h[i] = __float2half(Whh[(size_t)k * UNITS + n]);
}

__global__ void build_wx_kernel(const float* __restrict__ Wxh) {
    int i = blockIdx.x * blockDim.x + threadIdx.x;
    if (i >= UNITS * 128) return;
    int n = i >> 7;
    int k = i & 127;
    float v = (k < EDIM) ? Wxh[(size_t)k * UNITS + n] : 0.0f;
    __half hi = __float2half(v);
    g_WX_h[i] = hi;
    g_WX_l[i] = __float2half(v - __half2float(hi));
}

__global__ void init_h_kernel() {
    int i = blockIdx.x * blockDim.x + threadIdx.x;
    if (i < NCTA * 32) g_flag[i] = 0u;
    if (i >= BATCH * UNITS) return;
    g_H[0][i] = __float2half(0.0f);
}

// ---------------- table projection: g_EP = emb @ W_xh + b_h (hi/lo, one-shot) ----
__global__ __launch_bounds__(256, 2)
void proj_gemm(const float* __restrict__ emb, const float* __restrict__ bh) {
    extern __shared__ char smem[];
    const uint32_t su = smem_to_u32(smem);
    const int tid = threadIdx.x, wid = tid >> 5, lane = tid & 31;
    const int col0 = blockIdx.x * BN;
    const int r0   = blockIdx.y * BM;

    // zero A planes (pads k in [100,128) and rows >= NWORDS)
    {
        uint4 z = make_uint4(0, 0, 0, 0);
#pragma unroll
        for (int i = 0; i < 8; i++)
            *reinterpret_cast<uint4*>(smem + tid * 16 + i * 4096) = z;
    }
    // B planes via cp.async (disjoint region)
    {
#pragma unroll
        for (int i = 0; i < 8; i++) {
            int u = tid + i * 256;
            int p  = u >> 10;
            int rem = u & 1023;
            int ch = rem >> 9;
            int r  = (rem >> 3) & 63;
            int s  = rem & 7;
            uint32_t so = SWZ((uint32_t)(r * 128 + s * 16));
            const __half* wsrc = (p == 0 ? g_WX_h : g_WX_l) + (size_t)(col0 + r) * 128 + ch * 64;
            CP16(su + PB(p, ch) + so, (const char*)wsrc + s * 16);
        }
    }
    CP_COMMIT();
    __syncthreads();   // zero-fill visible before gather overwrites

    // vectorized A staging: 2 threads per row, float4 loads, half2 stores
    {
        const int row = tid >> 1, sub = tid & 1;
        const int gr = r0 + row;
        if (gr < NWORDS) {
            const float4* src = reinterpret_cast<const float4*>(emb + (size_t)gr * EDIM);
#pragma unroll
            for (int f4 = sub; f4 < 25; f4 += 2) {
                float4 v = __ldg(src + f4);
                int k = f4 * 4;
                int ch = k >> 6, kk = k & 63;
                uint32_t so = SWZ((uint32_t)(row * 128 + kk * 2));
                __half2 h0; h0.x = __float2half(v.x); h0.y = __float2half(v.y);
                __half2 h1; h1.x = __float2half(v.z); h1.y = __float2half(v.w);
                *reinterpret_cast<__half2*>(smem + PA(ch) + so)     = h0;
                *reinterpret_cast<__half2*>(smem + PA(ch) + so + 4) = h1;
            }
        }
    }
    CP_WAIT(0);
    __syncthreads();

    const int m_base = (wid & 3) * 32;
    const int n_base = (wid >> 2) * 32;
    const int a_row = lane & 15, a_kh = (lane >> 4) * 16;
    const int b_row = ((lane >> 4) << 3) + (lane & 7), b_kh = ((lane >> 3) & 1) * 16;
    const int lg = lane >> 2, tig = lane & 3;

    float acc[2][4][4];
#pragma unroll
    for (int mt = 0; mt < 2; mt++)
#pragma unroll
        for (int nt = 0; nt < 4; nt++)
#pragma unroll
            for (int q = 0; q < 4; q++) acc[mt][nt][q] = 0.0f;

#pragma unroll
    for (int ks = 0; ks < 7; ks++) {
        const int ch = ks >> 2;
        const int kb = (ks & 3) * 32;
        uint32_t A[2][4], Bh[4][2], Bl[4][2];
#pragma unroll
        for (int mt = 0; mt < 2; mt++) {
            uint32_t bo = SWZ((uint32_t)((m_base + mt * 16 + a_row) * 128 + kb + a_kh));
            LDSM_X4(A[mt][0], A[mt][1], A[mt][2], A[mt][3], su + PA(ch) + bo);
        }
#pragma unroll
        for (int np = 0; np < 2; np++) {
            uint32_t bo = SWZ((uint32_t)((n_base + np * 16 + b_row) * 128 + kb + b_kh));
            LDSM_X4(Bh[np * 2][0], Bh[np * 2][1], Bh[np * 2 + 1][0], Bh[np * 2 + 1][1],
                    su + PB(0, ch) + bo);
            LDSM_X4(Bl[np * 2][0], Bl[np * 2][1], Bl[np * 2 + 1][0], Bl[np * 2 + 1][1],
                    su + PB(1, ch) + bo);
        }
#pragma unroll
        for (int mt = 0; mt < 2; mt++)
#pragma unroll
            for (int nt = 0; nt < 4; nt++) {
                MMAF16(acc[mt][nt], A[mt][0], A[mt][1], A[mt][2], A[mt][3],
                       Bh[nt][0], Bh[nt][1]);
                MMAF16(acc[mt][nt], A[mt][0], A[mt][1], A[mt][2], A[mt][3],
                       Bl[nt][0], Bl[nt][1]);
            }
    }

#pragma unroll
    for (int mt = 0; mt < 2; mt++)
#pragma unroll
        for (int nt = 0; nt < 4; nt++) {
            const int col = col0 + n_base + nt * 8 + tig * 2;
            const float b0 = __ldg(bh + col);
            const float b1 = __ldg(bh + col + 1);
#pragma unroll
            for (int half = 0; half < 2; half++) {
                const int row = r0 + m_base + mt * 16 + lg + half * 8;
                if (row < NWORDS) {
                    float2 v;
                    v.x = acc[mt][nt][half * 2] + b0;
                    v.y = acc[mt][nt][half * 2 + 1] + b1;
                    *reinterpret_cast<float2*>(g_EP + (size_t)row * UNITS + col) = v;
                }
            }
        }
}

// ---------------- persistent recurrence: split-K(2), pair-cooperative A loads ----
__global__ __launch_bounds__(512, 1)
void rnn_persistent(const int* __restrict__ inputs) {
    extern __shared__ char smem[];
    const uint32_t su = smem_to_u32(smem);
    const int tid = threadIdx.x, wid = tid >> 5, lane = tid & 31;
    const int kg  = wid >> 3;                      // k-group 0/1
    const int wg  = wid & 7;
    const int bid = blockIdx.x;
    const int cidx = bid & 7;
    const int grp  = bid >> 3;
    const int col0 = cidx * BN, row0 = grp * BM;

    // resident B: W_hh single plane, 8 chunks
    {
#pragma unroll
        for (int i = 0; i < 8; i++) {
            int u = tid + i * 512;
            int rg = u >> 3, s = u & 7;
            int ch = rg >> 6, r = rg & 63;
            uint32_t so = SWZ((uint32_t)(r * 128 + s * 16));
            size_t gs = (size_t)(col0 + r) * UNITS + ch * 64;
            CP16(su + B_RES(ch) + so, (const char*)(g_Whh_h + gs) + s * 16);
        }
    }
    CP_COMMIT();
    // prefill A buffer 0 with zeros (H_0 own chunk, forwarded path)
    {
        uint4 z = make_uint4(0, 0, 0, 0);
        reinterpret_cast<uint4*>(smem + A_OFF(0))[tid]       = z;
        reinterpret_cast<uint4*>(smem + A_OFF(0))[tid + 512] = z;
    }
    CP_WAIT(0);
    __syncthreads();

    const int m_base = (wg & 3) * 32;
    const int n_base = (wg >> 2) * 32;
    const int mrow0  = m_base + (wg >> 2) * 16;    // this warp's 16-row load slice
    const int pair_id = 2 + kg * 4 + (wg & 3);     // named barrier per m-pair, ids 2..9
    const int a_row = lane & 15, a_kh = (lane >> 4) * 16;
    const int b_row = ((lane >> 4) << 3) + (lane & 7), b_kh = ((lane >> 3) & 1) * 16;
    const int lg = lane >> 2, tig = lane & 3;

    for (int t = 0; t < TLEN; t++) {
        const __half* __restrict__ Hsrc = g_H[t & 1];

        float acc[2][4][4];
#pragma unroll
        for (int mt = 0; mt < 2; mt++)
#pragma unroll
            for (int nt = 0; nt < 4; nt++)
#pragma unroll
                for (int q = 0; q < 4; q++) acc[mt][nt][q] = 0.0f;

        auto spin = [&](int kc) {
            const unsigned* fp = &g_flag[(grp * 8 + kc) * 32];
            unsigned v;
            do {
                asm volatile("ld.acquire.gpu.u32 %0, [%1];" : "=r"(v) : "l"(fp));
            } while ((int)v < t);
        };
        // pair-cooperative: this warp loads ITS 16 rows (mrow0..mrow0+16) of chunk kc.
        // The pair warp loads the other 16; BAR_PAIR after CP_WAIT joins the halves.
        auto load_A = [&](int kc, int buf) {
            const __half* sh = Hsrc + (size_t)(row0 + mrow0) * UNITS + kc * KC;
#pragma unroll
            for (int i = 0; i < 4; i++) {
                int u = lane + i * 32;           // 0..127
                int r = u >> 3, s = u & 7;       // r 0..15
                uint32_t so = SWZ((uint32_t)((mrow0 + r) * 128 + s * 16));
                CP16(su + A_OFF(buf) + so, (const char*)(sh + (size_t)r * UNITS) + s * 16);
            }
            CP_COMMIT();
        };

#define PROC_CHUNK(abuf, kc) do {                                             \
            const uint32_t ah_ = su + A_OFF(abuf);                            \
            const uint32_t bh_ = su + B_RES(kc);                              \
            _Pragma("unroll")                                                 \
            for (int ks_ = 0; ks_ < 4; ks_++) {                               \
                const int kb_ = ks_ * 32;                                     \
                uint32_t Af_[2][4], Bh_[4][2];                                \
                _Pragma("unroll")                                             \
                for (int mt_ = 0; mt_ < 2; mt_++) {                           \
                    uint32_t bo = SWZ((uint32_t)((m_base + mt_ * 16 + a_row)  \
                                                 * 128 + kb_ + a_kh));        \
                    LDSM_X4(Af_[mt_][0], Af_[mt_][1], Af_[mt_][2],            \
                            Af_[mt_][3], ah_ + bo);                           \
                }                                                             \
                _Pragma("unroll")                                             \
                for (int np_ = 0; np_ < 2; np_++) {                           \
                    uint32_t bo = SWZ((uint32_t)((n_base + np_ * 16 + b_row)  \
                                                 * 128 + kb_ + b_kh));        \
                    LDSM_X4(Bh_[np_ * 2][0], Bh_[np_ * 2][1],                 \
                            Bh_[np_ * 2 + 1][0], Bh_[np_ * 2 + 1][1],         \
                            bh_ + bo);                                        \
                }                                                             \
                _Pragma("unroll")                                             \
                for (int mt_ = 0; mt_ < 2; mt_++)                             \
                    _Pragma("unroll")                                         \
                    for (int nt_ = 0; nt_ < 4; nt_++)                         \
                        MMAF16(acc[mt_][nt_], Af_[mt_][0], Af_[mt_][1],       \
                               Af_[mt_][2], Af_[mt_][3],                      \
                               Bh_[nt_][0], Bh_[nt_][1]);                     \
            }                                                                 \
        } while (0)

        if (kg == 0) {
            const int k1 = (cidx + 1) & 7, k2 = (cidx + 2) & 7, k3 = (cidx + 3) & 7;
            spin(k1); load_A(k1, 1);
            spin(k2); load_A(k2, 2);
            PROC_CHUNK(0, cidx);               // own chunk, smem-forwarded
            CP_WAIT(1); BAR_PAIR(pair_id);      // k1 halves joined
            spin(k3); load_A(k3, 3);
            PROC_CHUNK(1, k1);
            CP_WAIT(1); BAR_PAIR(pair_id);      // k2 halves joined
            PROC_CHUNK(2, k2);
            CP_WAIT(0); BAR_PAIR(pair_id);      // k3 halves joined
            PROC_CHUNK(3, k3);

            BAR_CTA();                          // #1: stage ready (pairs with g1)

            // ---- combine + tanh + store + forward ----
            __half* __restrict__ Hdst = g_H[(t + 1) & 1];
            const float* stg = reinterpret_cast<const float*>(smem + STAGE_OFF);
#pragma unroll
            for (int mt = 0; mt < 2; mt++)
#pragma unroll
                for (int nt = 0; nt < 4; nt++) {
                    const int col_l = n_base + nt * 8 + tig * 2;
                    const int col   = col0 + col_l;
#pragma unroll
                    for (int half = 0; half < 2; half++) {
                        const int row_l = m_base + mt * 16 + lg + half * 8;
                        float2 s2 = *reinterpret_cast<const float2*>(
                                        stg + row_l * STG_STRIDE + col_l);
                        float v0 = tanh_fast(acc[mt][nt][half * 2 + 0] + s2.x);
                        float v1 = tanh_fast(acc[mt][nt][half * 2 + 1] + s2.y);
                        __half2 hp;
                        hp.x = __float2half(v0);
                        hp.y = __float2half(v1);
                        *reinterpret_cast<__half2*>(
                            Hdst + (size_t)(row0 + row_l) * UNITS + col) = hp;
                        uint32_t so = SWZ((uint32_t)(row_l * 128 + col_l * 2));
                        *reinterpret_cast<__half2*>(smem + A_OFF(0) + so) = hp;
                    }
                }

            BAR_CTA();                          // #2: forwarding + stores visible
            if (tid == 0) {
                __threadfence();
                unsigned* fp = &g_flag[(grp * 8 + cidx) * 32];
                asm volatile("st.release.gpu.u32 [%0], %1;"
                             :: "l"(fp), "r"((unsigned)(t + 1)) : "memory");
            }
        } else {
            // ---- EP gather (xw + bias, fp32) — issued early, consumed at stage ----
            float ep[2][4][4];
#pragma unroll
            for (int mt = 0; mt < 2; mt++)
#pragma unroll
                for (int half = 0; half < 2; half++) {
                    const int row = row0 + m_base + mt * 16 + lg + half * 8;
                    const int idx = __ldg(inputs + (size_t)row * TLEN + t);
                    const float* eprow = g_EP + (size_t)idx * UNITS + col0;
#pragma unroll
                    for (int nt = 0; nt < 4; nt++) {
                        float2 v = __ldg(reinterpret_cast<const float2*>(
                                             eprow + n_base + nt * 8 + tig * 2));
                        ep[mt][nt][half * 2]     = v.x;
                        ep[mt][nt][half * 2 + 1] = v.y;
                    }
                }

            const int k4 = (cidx + 4) & 7, k5 = (cidx + 5) & 7;
            const int k6 = (cidx + 6) & 7, k7 = (cidx + 7) & 7;
            spin(k4); load_A(k4, 4);
            spin(k5); load_A(k5, 5);
            spin(k6); load_A(k6, 6);
            CP_WAIT(2); BAR_PAIR(pair_id);      // k4 halves joined
            PROC_CHUNK(4, k4);
            spin(k7); load_A(k7, 7);
            CP_WAIT(2); BAR_PAIR(pair_id);      // k5 halves joined
            PROC_CHUNK(5, k5);
            CP_WAIT(1); BAR_PAIR(pair_id);      // k6 halves joined
            PROC_CHUNK(6, k6);
            CP_WAIT(0); BAR_PAIR(pair_id);      // k7 halves joined
            PROC_CHUNK(7, k7);

            BAR_G1();                           // all g1 A-reads of bufs 4-6 done
                                                // before stage overlay write

            // ---- stage partial acc + ep (overlays bufs 4..6) ----
            float* stg = reinterpret_cast<float*>(smem + STAGE_OFF);
#pragma unroll
            for (int mt = 0; mt < 2; mt++)
#pragma unroll
                for (int nt = 0; nt < 4; nt++) {
                    const int col_l = n_base + nt * 8 + tig * 2;
#pragma unroll
                    for (int half = 0; half < 2; half++) {
                        const int row_l = m_base + mt * 16 + lg + half * 8;
                        float2 w;
                        w.x = acc[mt][nt][half * 2 + 0] + ep[mt][nt][half * 2 + 0];
                        w.y = acc[mt][nt][half * 2 + 1] + ep[mt][nt][half * 2 + 1];
                        *reinterpret_cast<float2*>(
                            stg + row_l * STG_STRIDE + col_l) = w;
                    }
                }
            BAR_CTA();                          // #1: stage visible to g0
            BAR_CTA();                          // #2: g0 done; bufs reusable
        }
#undef PROC_CHUNK
    }
}

// ---------------- final logits ----------------
__global__ __launch_bounds__(256)
void final_logits_kernel(const float* __restrict__ Wout,
                         const float* __restrict__ bout,
                         float* __restrict__ out) {
    const __half* __restrict__ h = g_H[0];   // TLEN = 80 even -> plane 0
    int warp = threadIdx.x >> 5;
    int lane = threadIdx.x & 31;
    int row = blockIdx.x * 8 + warp;
    if (row >= BATCH) return;
    float s = 0.0f;
#pragma unroll
    for (int j = 0; j < UNITS / 32; j++) {
        int k = lane + j * 32;
        s += __half2float(h[(size_t)row * UNITS + k]) * Wout[k];
    }
#pragma unroll
    for (int o = 16; o; o >>= 1) s += __shfl_xor_sync(0xffffffff, s, o);
    if (lane == 0) out[row] = 1.0f / (1.0f + expf(-(s + bout[0])));
}

// ---------------- launch ----------------
extern "C" void kernel_launch(void* const* d_in, const int* in_sizes, int n_in,
                              void* d_out, int out_size) {
    const int*   inputs = (const int*)  d_in[0];
    const float* emb    = (const float*)d_in[1];
    const float* Wxh    = (const float*)d_in[2];
    const float* Whh    = (const float*)d_in[3];
    const float* bh     = (const float*)d_in[4];
    const float* Wout   = (const float*)d_in[5];
    const float* bout   = (const float*)d_in[6];
    float* out = (float*)d_out;

    cudaFuncSetAttribute(rnn_persistent,
                         cudaFuncAttributeMaxDynamicSharedMemorySize, SMEM_MAIN);
    cudaFuncSetAttribute(proj_gemm,
                         cudaFuncAttributeMaxDynamicSharedMemorySize, SMEM_PROJ);

    build_whh_kernel<<<(UNITS * UNITS + 255) / 256, 256>>>(Whh);
    build_wx_kernel<<<(UNITS * 128 + 255) / 256, 256>>>(Wxh);
    init_h_kernel<<<(BATCH * UNITS + 255) / 256, 256>>>();

    dim3 gp(UNITS / BN, (NWORDS + BM - 1) / BM);   // (8, 274)
    proj_gemm<<<gp, 256, SMEM_PROJ>>>(emb, bh);

    rnn_persistent<<<NCTA, 512, SMEM_MAIN>>>(inputs);

    final_logits_kernel<<<BATCH / 8, 256>>>(Wout, bout, out);
}

// round 14
// speedup vs baseline: 1.0794x; 1.0792x over previous
#include <cuda_runtime.h>
#include <cuda_fp16.h>
#include <cstdint>
#include <math.h>

// ---------------- problem dims ----------------
#define BATCH 2048
#define TLEN  80
#define EDIM  100
#define NWORDS 35000
#define UNITS 512
#define KC    64               // K chunk (64 fp16 = 128 B row)
#define BM    64               // rows per CTA (2 CTAs/SM co-residency)
#define BN    64
#define NCTA  256              // 32 row-groups x 8 col CTAs
#define GRPSZ 8

// ---------------- static device scratch ----------------
__device__ __half g_H[2][BATCH * UNITS];          // hidden state, fp16
__device__ __half g_Whh_h[UNITS * UNITS];         // W_hh single fp16 plane, [n][k]
__device__ __half g_WX_h[UNITS * 128];            // W_xh hi plane, [n][k pad 128]
__device__ __half g_WX_l[UNITS * 128];
__device__ float  g_EP[(size_t)NWORDS * UNITS];   // emb @ W_xh + b_h  (fp32)
__device__ unsigned g_flag[NCTA * 32];            // per (grp,col) flags, 128B stride

// ---------------- PTX helpers ----------------
__device__ __forceinline__ uint32_t smem_to_u32(const void* p) {
    uint32_t a;
    asm("{ .reg .u64 t; cvta.to.shared.u64 t, %1; cvt.u32.u64 %0, t; }" : "=r"(a) : "l"(p));
    return a;
}
__device__ __forceinline__ float tanh_fast(float x) {
    float r;
    asm("tanh.approx.f32 %0, %1;" : "=f"(r) : "f"(x));
    return r;
}
#define CP16(dst, src) \
    asm volatile("cp.async.cg.shared.global [%0], [%1], 16;" :: "r"(dst), "l"(src))
#define CP_COMMIT() asm volatile("cp.async.commit_group;" ::: "memory")
#define CP_WAIT(n)  asm volatile("cp.async.wait_group %0;" :: "n"(n) : "memory")

#define LDSM_X4(r0, r1, r2, r3, addr) \
    asm volatile("ldmatrix.sync.aligned.m8n8.x4.shared.b16 {%0,%1,%2,%3}, [%4];" \
                 : "=r"(r0), "=r"(r1), "=r"(r2), "=r"(r3) : "r"(addr))

#define MMAF16(d, a0, a1, a2, a3, b0, b1) \
    asm volatile("mma.sync.aligned.m16n8k16.row.col.f32.f16.f16.f32 " \
                 "{%0,%1,%2,%3}, {%4,%5,%6,%7}, {%8,%9}, {%0,%1,%2,%3};" \
                 : "+f"((d)[0]), "+f"((d)[1]), "+f"((d)[2]), "+f"((d)[3]) \
                 : "r"(a0), "r"(a1), "r"(a2), "r"(a3), "r"(b0), "r"(b1))

#define SWZ(bo) ((bo) ^ (((bo) >> 3) & 0x70))

#define BAR_CTA()    asm volatile("barrier.sync 0;" ::: "memory")
#define BAR_G1()     asm volatile("barrier.sync 1, 128;" ::: "memory")
#define BAR_PAIR(id) asm volatile("barrier.sync %0, 64;" :: "r"(id) : "memory")

// ---------------- SMEM layouts ----------------
// main: B resident 8 chunks x 8KB = 64KB; A 5 bufs x 8KB = 40KB (g0: 0-2, g1: 3-4)
// stage (g1 partial acc + ep, fp16, 64 x 72 = 9216B) overlays bufs 3-4 (after BAR_G1)
#define B_RES(c)     ((c) * 8192)
#define A_OFF(buf)   (65536 + (buf) * 8192)
#define STAGE_OFF    A_OFF(3)
#define STG_STRIDE   72                            // halves per row (144 B)
#define SMEM_MAIN    (65536 + 5 * 8192)            // 106496 -> 2 CTAs/SM
// proj: A fp16 2 chunks x 16KB = 32KB; B 2 planes x 2 chunks x 8KB = 32KB
#define PA(ch)       ((ch) * 16384)
#define PB(p, ch)    (32768 + ((p) * 2 + (ch)) * 8192)
#define SMEM_PROJ    65536

// ---------------- prep kernels ----------------
__global__ void build_whh_kernel(const float* __restrict__ Whh) {
    int i = blockIdx.x * blockDim.x + threadIdx.x;
    if (i >= UNITS * UNITS) return;
    int n = i / UNITS;
    int k = i - n * UNITS;
    g_Whh_h[i] = __float2half(Whh[(size_t)k * UNITS + n]);
}

__global__ void build_wx_kernel(const float* __restrict__ Wxh) {
    int i = blockIdx.x * blockDim.x + threadIdx.x;
    if (i >= UNITS * 128) return;
    int n = i >> 7;
    int k = i & 127;
    float v = (k < EDIM) ? Wxh[(size_t)k * UNITS + n] : 0.0f;
    __half hi = __float2half(v);
    g_WX_h[i] = hi;
    g_WX_l[i] = __float2half(v - __half2float(hi));
}

__global__ void init_h_kernel() {
    int i = blockIdx.x * blockDim.x + threadIdx.x;
    if (i < NCTA * 32) g_flag[i] = 0u;
    if (i >= BATCH * UNITS) return;
    g_H[0][i] = __float2half(0.0f);
}

// ---------------- table projection: g_EP = emb @ W_xh + b_h (hi/lo, one-shot) ----
__global__ __launch_bounds__(256, 2)
void proj_gemm(const float* __restrict__ emb, const float* __restrict__ bh) {
    extern __shared__ char smem[];
    const uint32_t su = smem_to_u32(smem);
    const int tid = threadIdx.x, wid = tid >> 5, lane = tid & 31;
    const int col0 = blockIdx.x * BN;
    const int r0   = blockIdx.y * 128;

    {
        uint4 z = make_uint4(0, 0, 0, 0);
#pragma unroll
        for (int i = 0; i < 8; i++)
            *reinterpret_cast<uint4*>(smem + tid * 16 + i * 4096) = z;
    }
    {
#pragma unroll
        for (int i = 0; i < 8; i++) {
            int u = tid + i * 256;
            int p  = u >> 10;
            int rem = u & 1023;
            int ch = rem >> 9;
            int r  = (rem >> 3) & 63;
            int s  = rem & 7;
            uint32_t so = SWZ((uint32_t)(r * 128 + s * 16));
            const __half* wsrc = (p == 0 ? g_WX_h : g_WX_l) + (size_t)(col0 + r) * 128 + ch * 64;
            CP16(su + PB(p, ch) + so, (const char*)wsrc + s * 16);
        }
    }
    CP_COMMIT();
    __syncthreads();

    {
        const int row = tid >> 1, sub = tid & 1;
        const int gr = r0 + row;
        if (gr < NWORDS) {
            const float4* src = reinterpret_cast<const float4*>(emb + (size_t)gr * EDIM);
#pragma unroll
            for (int f4 = sub; f4 < 25; f4 += 2) {
                float4 v = __ldg(src + f4);
                int k = f4 * 4;
                int ch = k >> 6, kk = k & 63;
                uint32_t so = SWZ((uint32_t)(row * 128 + kk * 2));
                __half2 h0; h0.x = __float2half(v.x); h0.y = __float2half(v.y);
                __half2 h1; h1.x = __float2half(v.z); h1.y = __float2half(v.w);
                *reinterpret_cast<__half2*>(smem + PA(ch) + so)     = h0;
                *reinterpret_cast<__half2*>(smem + PA(ch) + so + 4) = h1;
            }
        }
    }
    CP_WAIT(0);
    __syncthreads();

    const int m_base = (wid & 3) * 32;
    const int n_base = (wid >> 2) * 32;
    const int a_row = lane & 15, a_kh = (lane >> 4) * 16;
    const int b_row = ((lane >> 4) << 3) + (lane & 7), b_kh = ((lane >> 3) & 1) * 16;
    const int lg = lane >> 2, tig = lane & 3;

    float acc[2][4][4];
#pragma unroll
    for (int mt = 0; mt < 2; mt++)
#pragma unroll
        for (int nt = 0; nt < 4; nt++)
#pragma unroll
            for (int q = 0; q < 4; q++) acc[mt][nt][q] = 0.0f;

#pragma unroll
    for (int ks = 0; ks < 7; ks++) {
        const int ch = ks >> 2;
        const int kb = (ks & 3) * 32;
        uint32_t A[2][4], Bh[4][2], Bl[4][2];
#pragma unroll
        for (int mt = 0; mt < 2; mt++) {
            uint32_t bo = SWZ((uint32_t)((m_base + mt * 16 + a_row) * 128 + kb + a_kh));
            LDSM_X4(A[mt][0], A[mt][1], A[mt][2], A[mt][3], su + PA(ch) + bo);
        }
#pragma unroll
        for (int np = 0; np < 2; np++) {
            uint32_t bo = SWZ((uint32_t)((n_base + np * 16 + b_row) * 128 + kb + b_kh));
            LDSM_X4(Bh[np * 2][0], Bh[np * 2][1], Bh[np * 2 + 1][0], Bh[np * 2 + 1][1],
                    su + PB(0, ch) + bo);
            LDSM_X4(Bl[np * 2][0], Bl[np * 2][1], Bl[np * 2 + 1][0], Bl[np * 2 + 1][1],
                    su + PB(1, ch) + bo);
        }
#pragma unroll
        for (int mt = 0; mt < 2; mt++)
#pragma unroll
            for (int nt = 0; nt < 4; nt++) {
                MMAF16(acc[mt][nt], A[mt][0], A[mt][1], A[mt][2], A[mt][3],
                       Bh[nt][0], Bh[nt][1]);
                MMAF16(acc[mt][nt], A[mt][0], A[mt][1], A[mt][2], A[mt][3],
                       Bl[nt][0], Bl[nt][1]);
            }
    }

#pragma unroll
    for (int mt = 0; mt < 2; mt++)
#pragma unroll
        for (int nt = 0; nt < 4; nt++) {
            const int col = col0 + n_base + nt * 8 + tig * 2;
            const float b0 = __ldg(bh + col);
            const float b1 = __ldg(bh + col + 1);
#pragma unroll
            for (int half = 0; half < 2; half++) {
                const int row = r0 + m_base + mt * 16 + lg + half * 8;
                if (row < NWORDS) {
                    float2 v;
                    v.x = acc[mt][nt][half * 2] + b0;
                    v.y = acc[mt][nt][half * 2 + 1] + b1;
                    *reinterpret_cast<float2*>(g_EP + (size_t)row * UNITS + col) = v;
                }
            }
        }
}

// ---------------- persistent recurrence: BM=64, 2 CTAs/SM, split-K(2) ----------------
__global__ __launch_bounds__(256, 2)
void rnn_persistent(const int* __restrict__ inputs) {
    extern __shared__ char smem[];
    const uint32_t su = smem_to_u32(smem);
    const int tid = threadIdx.x, wid = tid >> 5, lane = tid & 31;
    const int kg  = wid >> 2;                      // k-group 0/1 (4 warps each)
    const int wg  = wid & 3;
    const int bid = blockIdx.x;
    const int cidx = bid & 7;
    const int grp  = bid >> 3;                     // 0..31
    const int col0 = cidx * BN, row0 = grp * BM;

    // resident B: W_hh single plane, 8 chunks (64KB, 4096 16B units)
    {
#pragma unroll
        for (int i = 0; i < 16; i++) {
            int u = tid + i * 256;
            int rg = u >> 3, s = u & 7;
            int ch = rg >> 6, r = rg & 63;
            uint32_t so = SWZ((uint32_t)(r * 128 + s * 16));
            size_t gs = (size_t)(col0 + r) * UNITS + ch * 64;
            CP16(su + B_RES(ch) + so, (const char*)(g_Whh_h + gs) + s * 16);
        }
    }
    CP_COMMIT();
    // prefill A buffer 0 with zeros (H_0 own chunk, forwarded path): 8KB
    {
        uint4 z = make_uint4(0, 0, 0, 0);
        reinterpret_cast<uint4*>(smem + A_OFF(0))[tid]       = z;
        reinterpret_cast<uint4*>(smem + A_OFF(0))[tid + 256] = z;
    }
    CP_WAIT(0);
    __syncthreads();

    const int m_base = (wg & 1) * 32;
    const int n_base = (wg >> 1) * 32;
    const int mrow0  = m_base + (wg >> 1) * 16;    // this warp's 16-row load slice
    const int pair_id = 2 + kg * 2 + (wg & 1);     // named barrier per m-pair, ids 2..5
    const int a_row = lane & 15, a_kh = (lane >> 4) * 16;
    const int b_row = ((lane >> 4) << 3) + (lane & 7), b_kh = ((lane >> 3) & 1) * 16;
    const int lg = lane >> 2, tig = lane & 3;

    for (int t = 0; t < TLEN; t++) {
        const __half* __restrict__ Hsrc = g_H[t & 1];

        float acc[2][4][4];
#pragma unroll
        for (int mt = 0; mt < 2; mt++)
#pragma unroll
            for (int nt = 0; nt < 4; nt++)
#pragma unroll
                for (int q = 0; q < 4; q++) acc[mt][nt][q] = 0.0f;

        auto spin = [&](int kc) {
            const unsigned* fp = &g_flag[(grp * 8 + kc) * 32];
            unsigned v;
            do {
                asm volatile("ld.acquire.gpu.u32 %0, [%1];" : "=r"(v) : "l"(fp));
            } while ((int)v < t);
        };
        // pair-cooperative: this warp loads its 16 rows of chunk kc (2KB = 128 units)
        auto load_A = [&](int kc, int buf) {
            const __half* sh = Hsrc + (size_t)(row0 + mrow0) * UNITS + kc * KC;
#pragma unroll
            for (int i = 0; i < 4; i++) {
                int u = lane + i * 32;           // 0..127
                int r = u >> 3, s = u & 7;       // r 0..15
                uint32_t so = SWZ((uint32_t)((mrow0 + r) * 128 + s * 16));
                CP16(su + A_OFF(buf) + so, (const char*)(sh + (size_t)r * UNITS) + s * 16);
            }
            CP_COMMIT();
        };

#define PROC_CHUNK(abuf, kc) do {                                             \
            const uint32_t ah_ = su + A_OFF(abuf);                            \
            const uint32_t bh_ = su + B_RES(kc);                              \
            _Pragma("unroll")                                                 \
            for (int ks_ = 0; ks_ < 4; ks_++) {                               \
                const int kb_ = ks_ * 32;                                     \
                uint32_t Af_[2][4], Bh_[4][2];                                \
                _Pragma("unroll")                                             \
                for (int mt_ = 0; mt_ < 2; mt_++) {                           \
                    uint32_t bo = SWZ((uint32_t)((m_base + mt_ * 16 + a_row)  \
                                                 * 128 + kb_ + a_kh));        \
                    LDSM_X4(Af_[mt_][0], Af_[mt_][1], Af_[mt_][2],            \
                            Af_[mt_][3], ah_ + bo);                           \
                }                                                             \
                _Pragma("unroll")                                             \
                for (int np_ = 0; np_ < 2; np_++) {                           \
                    uint32_t bo = SWZ((uint32_t)((n_base + np_ * 16 + b_row)  \
                                                 * 128 + kb_ + b_kh));        \
                    LDSM_X4(Bh_[np_ * 2][0], Bh_[np_ * 2][1],                 \
                            Bh_[np_ * 2 + 1][0], Bh_[np_ * 2 + 1][1],         \
                            bh_ + bo);                                        \
                }                                                             \
                _Pragma("unroll")                                             \
                for (int mt_ = 0; mt_ < 2; mt_++)                             \
                    _Pragma("unroll")                                         \
                    for (int nt_ = 0; nt_ < 4; nt_++)                         \
                        MMAF16(acc[mt_][nt_], Af_[mt_][0], Af_[mt_][1],       \
                               Af_[mt_][2], Af_[mt_][3],                      \
                               Bh_[nt_][0], Bh_[nt_][1]);                     \
            }                                                                 \
        } while (0)

        if (kg == 0) {
            // bufs {0,1,2}; buf0 holds own chunk (forwarded last step)
            const int k1 = (cidx + 1) & 7, k2 = (cidx + 2) & 7, k3 = (cidx + 3) & 7;
            spin(k1); load_A(k1, 1);                 // commit 1
            spin(k2); load_A(k2, 2);                 // commit 2
            PROC_CHUNK(0, cidx);
            CP_WAIT(1); BAR_PAIR(pair_id);           // k1 halves joined
            PROC_CHUNK(1, k1);
            BAR_PAIR(pair_id);                       // pair done reading buf1
            spin(k3); load_A(k3, 1);                 // commit 3 -> buf1
            CP_WAIT(1); BAR_PAIR(pair_id);           // k2 joined (commits 1,2 done)
            PROC_CHUNK(2, k2);
            CP_WAIT(0); BAR_PAIR(pair_id);           // k3 joined
            PROC_CHUNK(1, k3);

            BAR_CTA();                               // #1: stage ready

            // ---- combine + tanh + store + forward ----
            __half* __restrict__ Hdst = g_H[(t + 1) & 1];
            const __half* stg = reinterpret_cast<const __half*>(smem + STAGE_OFF);
#pragma unroll
            for (int mt = 0; mt < 2; mt++)
#pragma unroll
                for (int nt = 0; nt < 4; nt++) {
                    const int col_l = n_base + nt * 8 + tig * 2;
                    const int col   = col0 + col_l;
#pragma unroll
                    for (int half = 0; half < 2; half++) {
                        const int row_l = m_base + mt * 16 + lg + half * 8;
                        __half2 s2 = *reinterpret_cast<const __half2*>(
                                         stg + row_l * STG_STRIDE + col_l);
                        float v0 = tanh_fast(acc[mt][nt][half * 2 + 0] + __half2float(s2.x));
                        float v1 = tanh_fast(acc[mt][nt][half * 2 + 1] + __half2float(s2.y));
                        __half2 hp;
                        hp.x = __float2half(v0);
                        hp.y = __float2half(v1);
                        *reinterpret_cast<__half2*>(
                            Hdst + (size_t)(row0 + row_l) * UNITS + col) = hp;
                        uint32_t so = SWZ((uint32_t)(row_l * 128 + col_l * 2));
                        *reinterpret_cast<__half2*>(smem + A_OFF(0) + so) = hp;
                    }
                }

            BAR_CTA();                               // #2: forwarding + stores visible
            if (tid == 0) {
                __threadfence();
                unsigned* fp = &g_flag[(grp * 8 + cidx) * 32];
                asm volatile("st.release.gpu.u32 [%0], %1;"
                             :: "l"(fp), "r"((unsigned)(t + 1)) : "memory");
            }
        } else {
            // ---- EP gather (xw + bias, fp32) — issued early, consumed at stage ----
            float ep[2][4][4];
#pragma unroll
            for (int mt = 0; mt < 2; mt++)
#pragma unroll
                for (int half = 0; half < 2; half++) {
                    const int row = row0 + m_base + mt * 16 + lg + half * 8;
                    const int idx = __ldg(inputs + (size_t)row * TLEN + t);
                    const float* eprow = g_EP + (size_t)idx * UNITS + col0;
#pragma unroll
                    for (int nt = 0; nt < 4; nt++) {
                        float2 v = __ldg(reinterpret_cast<const float2*>(
                                             eprow + n_base + nt * 8 + tig * 2));
                        ep[mt][nt][half * 2]     = v.x;
                        ep[mt][nt][half * 2 + 1] = v.y;
                    }
                }

            // bufs {3,4}
            const int k4 = (cidx + 4) & 7, k5 = (cidx + 5) & 7;
            const int k6 = (cidx + 6) & 7, k7 = (cidx + 7) & 7;
            spin(k4); load_A(k4, 3);                 // c1
            spin(k5); load_A(k5, 4);                 // c2
            CP_WAIT(1); BAR_PAIR(pair_id);           // k4 joined
            PROC_CHUNK(3, k4);
            BAR_PAIR(pair_id);                       // buf3 free
            spin(k6); load_A(k6, 3);                 // c3
            CP_WAIT(1); BAR_PAIR(pair_id);           // k5 joined (c1,c2 done)
            PROC_CHUNK(4, k5);
            BAR_PAIR(pair_id);                       // buf4 free
            spin(k7); load_A(k7, 4);                 // c4
            CP_WAIT(1); BAR_PAIR(pair_id);           // k6 joined (c3 done)
            PROC_CHUNK(3, k6);
            CP_WAIT(0); BAR_PAIR(pair_id);           // k7 joined
            PROC_CHUNK(4, k7);

            BAR_G1();                                // all g1 reads of bufs 3-4 done

            // ---- stage partial acc + ep (fp16, overlays bufs 3-4) ----
            __half* stg = reinterpret_cast<__half*>(smem + STAGE_OFF);
#pragma unroll
            for (int mt = 0; mt < 2; mt++)
#pragma unroll
                for (int nt = 0; nt < 4; nt++) {
                    const int col_l = n_base + nt * 8 + tig * 2;
#pragma unroll
                    for (int half = 0; half < 2; half++) {
                        const int row_l = m_base + mt * 16 + lg + half * 8;
                        __half2 w;
                        w.x = __float2half(acc[mt][nt][half * 2 + 0]
                                           + ep[mt][nt][half * 2 + 0]);
                        w.y = __float2half(acc[mt][nt][half * 2 + 1]
                                           + ep[mt][nt][half * 2 + 1]);
                        *reinterpret_cast<__half2*>(
                            stg + row_l * STG_STRIDE + col_l) = w;
                    }
                }
            BAR_CTA();                               // #1: stage visible to g0
            BAR_CTA();                               // #2: g0 done; bufs reusable
        }
#undef PROC_CHUNK
    }
}

// ---------------- final logits ----------------
__global__ __launch_bounds__(256)
void final_logits_kernel(const float* __restrict__ Wout,
                         const float* __restrict__ bout,
                         float* __restrict__ out) {
    const __half* __restrict__ h = g_H[0];   // TLEN = 80 even -> plane 0
    int warp = threadIdx.x >> 5;
    int lane = threadIdx.x & 31;
    int row = blockIdx.x * 8 + warp;
    if (row >= BATCH) return;
    float s = 0.0f;
#pragma unroll
    for (int j = 0; j < UNITS / 32; j++) {
        int k = lane + j * 32;
        s += __half2float(h[(size_t)row * UNITS + k]) * Wout[k];
    }
#pragma unroll
    for (int o = 16; o; o >>= 1) s += __shfl_xor_sync(0xffffffff, s, o);
    if (lane == 0) out[row] = 1.0f / (1.0f + expf(-(s + bout[0])));
}

// ---------------- launch ----------------
extern "C" void kernel_launch(void* const* d_in, const int* in_sizes, int n_in,
                              void* d_out, int out_size) {
    const int*   inputs = (const int*)  d_in[0];
    const float* emb    = (const float*)d_in[1];
    const float* Wxh    = (const float*)d_in[2];
    const float* Whh    = (const float*)d_in[3];
    const float* bh     = (const float*)d_in[4];
    const float* Wout   = (const float*)d_in[5];
    const float* bout   = (const float*)d_in[6];
    float* out = (float*)d_out;

    cudaFuncSetAttribute(rnn_persistent,
                         cudaFuncAttributeMaxDynamicSharedMemorySize, SMEM_MAIN);
    cudaFuncSetAttribute(proj_gemm,
                         cudaFuncAttributeMaxDynamicSharedMemorySize, SMEM_PROJ);

    build_whh_kernel<<<(UNITS * UNITS + 255) / 256, 256>>>(Whh);
    build_wx_kernel<<<(UNITS * 128 + 255) / 256, 256>>>(Wxh);
    init_h_kernel<<<(BATCH * UNITS + 255) / 256, 256>>>();

    dim3 gp(UNITS / BN, (NWORDS + 127) / 128);   // (8, 274)
    proj_gemm<<<gp, 256, SMEM_PROJ>>>(emb, bh);

    rnn_persistent<<<NCTA, 256, SMEM_MAIN>>>(inputs);

    final_logits_kernel<<<BATCH / 8, 256>>>(Wout, bout, out);
}

// round 15
// speedup vs baseline: 1.0872x; 1.0072x over previous
#include <cuda_runtime.h>
#include <cuda_fp16.h>
#include <cstdint>
#include <math.h>

// ---------------- problem dims ----------------
#define BATCH 2048
#define TLEN  80
#define EDIM  100
#define NWORDS 35000
#define UNITS 512
#define KC    64               // K chunk (64 fp16 = 128 B row)
#define BM    64               // rows per CTA (2 CTAs/SM co-residency)
#define BN    64
#define NCTA  256              // 32 row-groups x 8 col CTAs
#define GRPSZ 8

// ---------------- static device scratch ----------------
__device__ __half g_H[2][BATCH * UNITS];          // hidden state, fp16
__device__ __half g_Whh_h[UNITS * UNITS];         // W_hh single fp16 plane, [n][k]
__device__ __half g_WX_h[UNITS * 128];            // W_xh single fp16 plane, [n][k pad 128]
__device__ float  g_EP[(size_t)NWORDS * UNITS];   // emb @ W_xh + b_h  (fp32)
__device__ unsigned g_flag[NCTA * 32];            // per (grp,col) flags, 128B stride

// ---------------- PTX helpers ----------------
__device__ __forceinline__ uint32_t smem_to_u32(const void* p) {
    uint32_t a;
    asm("{ .reg .u64 t; cvta.to.shared.u64 t, %1; cvt.u32.u64 %0, t; }" : "=r"(a) : "l"(p));
    return a;
}
__device__ __forceinline__ float tanh_fast(float x) {
    float r;
    asm("tanh.approx.f32 %0, %1;" : "=f"(r) : "f"(x));
    return r;
}
#define CP16(dst, src) \
    asm volatile("cp.async.cg.shared.global [%0], [%1], 16;" :: "r"(dst), "l"(src))
#define CP_COMMIT() asm volatile("cp.async.commit_group;" ::: "memory")
#define CP_WAIT(n)  asm volatile("cp.async.wait_group %0;" :: "n"(n) : "memory")

#define LDSM_X4(r0, r1, r2, r3, addr) \
    asm volatile("ldmatrix.sync.aligned.m8n8.x4.shared.b16 {%0,%1,%2,%3}, [%4];" \
                 : "=r"(r0), "=r"(r1), "=r"(r2), "=r"(r3) : "r"(addr))

#define MMAF16(d, a0, a1, a2, a3, b0, b1) \
    asm volatile("mma.sync.aligned.m16n8k16.row.col.f32.f16.f16.f32 " \
                 "{%0,%1,%2,%3}, {%4,%5,%6,%7}, {%8,%9}, {%0,%1,%2,%3};" \
                 : "+f"((d)[0]), "+f"((d)[1]), "+f"((d)[2]), "+f"((d)[3]) \
                 : "r"(a0), "r"(a1), "r"(a2), "r"(a3), "r"(b0), "r"(b1))

#define SWZ(bo) ((bo) ^ (((bo) >> 3) & 0x70))

#define BAR_CTA()    asm volatile("barrier.sync 0;" ::: "memory")
#define BAR_G1()     asm volatile("barrier.sync 1, 128;" ::: "memory")
#define BAR_PAIR(id) asm volatile("barrier.sync %0, 64;" :: "r"(id) : "memory")

// ---------------- SMEM layouts ----------------
// main: B resident 8 chunks x 8KB = 64KB; A 5 bufs x 8KB = 40KB (g0: 0-2, g1: 3-4)
// stage (g1 partial acc + ep, fp16, 64 x 72 = 9216B) overlays bufs 3-4 (after BAR_G1)
#define B_RES(c)     ((c) * 8192)
#define A_OFF(buf)   (65536 + (buf) * 8192)
#define STAGE_OFF    A_OFF(3)
#define STG_STRIDE   72                            // halves per row (144 B)
#define SMEM_MAIN    (65536 + 5 * 8192)            // 106496 -> 2 CTAs/SM
// proj: A fp16 2 chunks x 16KB = 32KB; B single plane 2 chunks x 8KB = 16KB
#define PA(ch)       ((ch) * 16384)
#define PB(ch)       (32768 + (ch) * 8192)
#define SMEM_PROJ    49152

// ---------------- prep kernels ----------------
__global__ void build_whh_kernel(const float* __restrict__ Whh) {
    int i = blockIdx.x * blockDim.x + threadIdx.x;
    if (i >= UNITS * UNITS) return;
    int n = i / UNITS;
    int k = i - n * UNITS;
    g_Whh_h[i] = __float2half(Whh[(size_t)k * UNITS + n]);
}

__global__ void build_wx_kernel(const float* __restrict__ Wxh) {
    int i = blockIdx.x * blockDim.x + threadIdx.x;
    if (i >= UNITS * 128) return;
    int n = i >> 7;
    int k = i & 127;
    float v = (k < EDIM) ? Wxh[(size_t)k * UNITS + n] : 0.0f;
    g_WX_h[i] = __float2half(v);
}

__global__ void init_h_kernel() {
    int i = blockIdx.x * blockDim.x + threadIdx.x;
    if (i < NCTA * 32) g_flag[i] = 0u;
    if (i >= BATCH * UNITS) return;
    g_H[0][i] = __float2half(0.0f);
}

// ---------------- table projection: g_EP = emb @ W_xh + b_h (single plane) ----
__global__ __launch_bounds__(256, 2)
void proj_gemm(const float* __restrict__ emb, const float* __restrict__ bh) {
    extern __shared__ char smem[];
    const uint32_t su = smem_to_u32(smem);
    const int tid = threadIdx.x, wid = tid >> 5, lane = tid & 31;
    const int col0 = blockIdx.x * BN;
    const int r0   = blockIdx.y * 128;

    // zero A planes (pads k in [100,128) and rows >= NWORDS)
    {
        uint4 z = make_uint4(0, 0, 0, 0);
#pragma unroll
        for (int i = 0; i < 8; i++)
            *reinterpret_cast<uint4*>(smem + tid * 16 + i * 4096) = z;
    }
    // B plane via cp.async (1024 16B units)
    {
#pragma unroll
        for (int i = 0; i < 4; i++) {
            int u = tid + i * 256;
            int ch = u >> 9;
            int r  = (u >> 3) & 63;
            int s  = u & 7;
            uint32_t so = SWZ((uint32_t)(r * 128 + s * 16));
            const __half* wsrc = g_WX_h + (size_t)(col0 + r) * 128 + ch * 64;
            CP16(su + PB(ch) + so, (const char*)wsrc + s * 16);
        }
    }
    CP_COMMIT();
    __syncthreads();   // zero-fill visible before gather overwrites

    // vectorized A staging: 2 threads per row, float4 loads, half2 stores
    {
        const int row = tid >> 1, sub = tid & 1;
        const int gr = r0 + row;
        if (gr < NWORDS) {
            const float4* src = reinterpret_cast<const float4*>(emb + (size_t)gr * EDIM);
#pragma unroll
            for (int f4 = sub; f4 < 25; f4 += 2) {
                float4 v = __ldg(src + f4);
                int k = f4 * 4;
                int ch = k >> 6, kk = k & 63;
                uint32_t so = SWZ((uint32_t)(row * 128 + kk * 2));
                __half2 h0; h0.x = __float2half(v.x); h0.y = __float2half(v.y);
                __half2 h1; h1.x = __float2half(v.z); h1.y = __float2half(v.w);
                *reinterpret_cast<__half2*>(smem + PA(ch) + so)     = h0;
                *reinterpret_cast<__half2*>(smem + PA(ch) + so + 4) = h1;
            }
        }
    }
    CP_WAIT(0);
    __syncthreads();

    const int m_base = (wid & 3) * 32;
    const int n_base = (wid >> 2) * 32;
    const int a_row = lane & 15, a_kh = (lane >> 4) * 16;
    const int b_row = ((lane >> 4) << 3) + (lane & 7), b_kh = ((lane >> 3) & 1) * 16;
    const int lg = lane >> 2, tig = lane & 3;

    float acc[2][4][4];
#pragma unroll
    for (int mt = 0; mt < 2; mt++)
#pragma unroll
        for (int nt = 0; nt < 4; nt++)
#pragma unroll
            for (int q = 0; q < 4; q++) acc[mt][nt][q] = 0.0f;

#pragma unroll
    for (int ks = 0; ks < 7; ks++) {
        const int ch = ks >> 2;
        const int kb = (ks & 3) * 32;
        uint32_t A[2][4], Bh[4][2];
#pragma unroll
        for (int mt = 0; mt < 2; mt++) {
            uint32_t bo = SWZ((uint32_t)((m_base + mt * 16 + a_row) * 128 + kb + a_kh));
            LDSM_X4(A[mt][0], A[mt][1], A[mt][2], A[mt][3], su + PA(ch) + bo);
        }
#pragma unroll
        for (int np = 0; np < 2; np++) {
            uint32_t bo = SWZ((uint32_t)((n_base + np * 16 + b_row) * 128 + kb + b_kh));
            LDSM_X4(Bh[np * 2][0], Bh[np * 2][1], Bh[np * 2 + 1][0], Bh[np * 2 + 1][1],
                    su + PB(ch) + bo);
        }
#pragma unroll
        for (int mt = 0; mt < 2; mt++)
#pragma unroll
            for (int nt = 0; nt < 4; nt++)
                MMAF16(acc[mt][nt], A[mt][0], A[mt][1], A[mt][2], A[mt][3],
                       Bh[nt][0], Bh[nt][1]);
    }

#pragma unroll
    for (int mt = 0; mt < 2; mt++)
#pragma unroll
        for (int nt = 0; nt < 4; nt++) {
            const int col = col0 + n_base + nt * 8 + tig * 2;
            const float b0 = __ldg(bh + col);
            const float b1 = __ldg(bh + col + 1);
#pragma unroll
            for (int half = 0; half < 2; half++) {
                const int row = r0 + m_base + mt * 16 + lg + half * 8;
                if (row < NWORDS) {
                    float2 v;
                    v.x = acc[mt][nt][half * 2] + b0;
                    v.y = acc[mt][nt][half * 2 + 1] + b1;
                    *reinterpret_cast<float2*>(g_EP + (size_t)row * UNITS + col) = v;
                }
            }
        }
}

// ---------------- persistent recurrence: BM=64, 2 CTAs/SM, split-K 5/3 ----------------
__global__ __launch_bounds__(256, 2)
void rnn_persistent(const int* __restrict__ inputs) {
    extern __shared__ char smem[];
    const uint32_t su = smem_to_u32(smem);
    const int tid = threadIdx.x, wid = tid >> 5, lane = tid & 31;
    const int kg  = wid >> 2;                      // k-group 0/1 (4 warps each)
    const int wg  = wid & 3;
    const int bid = blockIdx.x;
    const int cidx = bid & 7;
    const int grp  = bid >> 3;                     // 0..31
    const int col0 = cidx * BN, row0 = grp * BM;

    // resident B: W_hh single plane, 8 chunks (64KB, 4096 16B units)
    {
#pragma unroll
        for (int i = 0; i < 16; i++) {
            int u = tid + i * 256;
            int rg = u >> 3, s = u & 7;
            int ch = rg >> 6, r = rg & 63;
            uint32_t so = SWZ((uint32_t)(r * 128 + s * 16));
            size_t gs = (size_t)(col0 + r) * UNITS + ch * 64;
            CP16(su + B_RES(ch) + so, (const char*)(g_Whh_h + gs) + s * 16);
        }
    }
    CP_COMMIT();
    // prefill A buffer 0 with zeros (H_0 own chunk, forwarded path): 8KB
    {
        uint4 z = make_uint4(0, 0, 0, 0);
        reinterpret_cast<uint4*>(smem + A_OFF(0))[tid]       = z;
        reinterpret_cast<uint4*>(smem + A_OFF(0))[tid + 256] = z;
    }
    CP_WAIT(0);
    __syncthreads();

    const int m_base = (wg & 1) * 32;
    const int n_base = (wg >> 1) * 32;
    const int mrow0  = m_base + (wg >> 1) * 16;    // this warp's 16-row load slice
    const int pair_id = 2 + kg * 2 + (wg & 1);     // named barrier per m-pair, ids 2..5
    const int a_row = lane & 15, a_kh = (lane >> 4) * 16;
    const int b_row = ((lane >> 4) << 3) + (lane & 7), b_kh = ((lane >> 3) & 1) * 16;
    const int lg = lane >> 2, tig = lane & 3;

    for (int t = 0; t < TLEN; t++) {
        const __half* __restrict__ Hsrc = g_H[t & 1];

        float acc[2][4][4];
#pragma unroll
        for (int mt = 0; mt < 2; mt++)
#pragma unroll
            for (int nt = 0; nt < 4; nt++)
#pragma unroll
                for (int q = 0; q < 4; q++) acc[mt][nt][q] = 0.0f;

        auto spin = [&](int kc) {
            const unsigned* fp = &g_flag[(grp * 8 + kc) * 32];
            unsigned v;
            do {
                asm volatile("ld.acquire.gpu.u32 %0, [%1];" : "=r"(v) : "l"(fp));
            } while ((int)v < t);
        };
        // pair-cooperative: this warp loads its 16 rows of chunk kc (2KB = 128 units)
        auto load_A = [&](int kc, int buf) {
            const __half* sh = Hsrc + (size_t)(row0 + mrow0) * UNITS + kc * KC;
#pragma unroll
            for (int i = 0; i < 4; i++) {
                int u = lane + i * 32;           // 0..127
                int r = u >> 3, s = u & 7;       // r 0..15
                uint32_t so = SWZ((uint32_t)((mrow0 + r) * 128 + s * 16));
                CP16(su + A_OFF(buf) + so, (const char*)(sh + (size_t)r * UNITS) + s * 16);
            }
            CP_COMMIT();
        };

#define PROC_CHUNK(abuf, kc) do {                                             \
            const uint32_t ah_ = su + A_OFF(abuf);                            \
            const uint32_t bh_ = su + B_RES(kc);                              \
            _Pragma("unroll")                                                 \
            for (int ks_ = 0; ks_ < 4; ks_++) {                               \
                const int kb_ = ks_ * 32;                                     \
                uint32_t Af_[2][4], Bh_[4][2];                                \
                _Pragma("unroll")                                             \
                for (int mt_ = 0; mt_ < 2; mt_++) {                           \
                    uint32_t bo = SWZ((uint32_t)((m_base + mt_ * 16 + a_row)  \
                                                 * 128 + kb_ + a_kh));        \
                    LDSM_X4(Af_[mt_][0], Af_[mt_][1], Af_[mt_][2],            \
                            Af_[mt_][3], ah_ + bo);                           \
                }                                                             \
                _Pragma("unroll")                                             \
                for (int np_ = 0; np_ < 2; np_++) {                           \
                    uint32_t bo = SWZ((uint32_t)((n_base + np_ * 16 + b_row)  \
                                                 * 128 + kb_ + b_kh));        \
                    LDSM_X4(Bh_[np_ * 2][0], Bh_[np_ * 2][1],                 \
                            Bh_[np_ * 2 + 1][0], Bh_[np_ * 2 + 1][1],         \
                            bh_ + bo);                                        \
                }                                                             \
                _Pragma("unroll")                                             \
                for (int mt_ = 0; mt_ < 2; mt_++)                             \
                    _Pragma("unroll")                                         \
                    for (int nt_ = 0; nt_ < 4; nt_++)                         \
                        MMAF16(acc[mt_][nt_], Af_[mt_][0], Af_[mt_][1],       \
                               Af_[mt_][2], Af_[mt_][3],                      \
                               Bh_[nt_][0], Bh_[nt_][1]);                     \
            }                                                                 \
        } while (0)

        if (kg == 0) {
            // ---- 5 chunks: cidx (forwarded, buf0) + k1..k4, bufs {1,2} cycled ----
            const int k1 = (cidx + 1) & 7, k2 = (cidx + 2) & 7;
            const int k3 = (cidx + 3) & 7, k4 = (cidx + 4) & 7;
            spin(k1); load_A(k1, 1);                 // commit 1
            spin(k2); load_A(k2, 2);                 // commit 2
            PROC_CHUNK(0, cidx);
            CP_WAIT(1); BAR_PAIR(pair_id);           // k1 halves joined
            PROC_CHUNK(1, k1);
            BAR_PAIR(pair_id);                       // pair done reading buf1
            spin(k3); load_A(k3, 1);                 // commit 3
            CP_WAIT(1); BAR_PAIR(pair_id);           // k2 joined
            PROC_CHUNK(2, k2);
            BAR_PAIR(pair_id);                       // pair done reading buf2
            spin(k4); load_A(k4, 2);                 // commit 4
            CP_WAIT(1); BAR_PAIR(pair_id);           // k3 joined
            PROC_CHUNK(1, k3);
            CP_WAIT(0); BAR_PAIR(pair_id);           // k4 joined
            PROC_CHUNK(2, k4);

            BAR_CTA();                               // #1: stage ready

            // ---- combine + tanh + store + forward ----
            __half* __restrict__ Hdst = g_H[(t + 1) & 1];
            const __half* stg = reinterpret_cast<const __half*>(smem + STAGE_OFF);
#pragma unroll
            for (int mt = 0; mt < 2; mt++)
#pragma unroll
                for (int nt = 0; nt < 4; nt++) {
                    const int col_l = n_base + nt * 8 + tig * 2;
                    const int col   = col0 + col_l;
#pragma unroll
                    for (int half = 0; half < 2; half++) {
                        const int row_l = m_base + mt * 16 + lg + half * 8;
                        __half2 s2 = *reinterpret_cast<const __half2*>(
                                         stg + row_l * STG_STRIDE + col_l);
                        float v0 = tanh_fast(acc[mt][nt][half * 2 + 0] + __half2float(s2.x));
                        float v1 = tanh_fast(acc[mt][nt][half * 2 + 1] + __half2float(s2.y));
                        __half2 hp;
                        hp.x = __float2half(v0);
                        hp.y = __float2half(v1);
                        *reinterpret_cast<__half2*>(
                            Hdst + (size_t)(row0 + row_l) * UNITS + col) = hp;
                        uint32_t so = SWZ((uint32_t)(row_l * 128 + col_l * 2));
                        *reinterpret_cast<__half2*>(smem + A_OFF(0) + so) = hp;
                    }
                }

            BAR_CTA();                               // #2: forwarding + stores visible
            if (tid == 0) {
                __threadfence();
                unsigned* fp = &g_flag[(grp * 8 + cidx) * 32];
                asm volatile("st.release.gpu.u32 [%0], %1;"
                             :: "l"(fp), "r"((unsigned)(t + 1)) : "memory");
            }
        } else {
            // ---- EP gather (xw + bias, fp32) — issued early, consumed at stage ----
            float ep[2][4][4];
#pragma unroll
            for (int mt = 0; mt < 2; mt++)
#pragma unroll
                for (int half = 0; half < 2; half++) {
                    const int row = row0 + m_base + mt * 16 + lg + half * 8;
                    const int idx = __ldg(inputs + (size_t)row * TLEN + t);
                    const float* eprow = g_EP + (size_t)idx * UNITS + col0;
#pragma unroll
                    for (int nt = 0; nt < 4; nt++) {
                        float2 v = __ldg(reinterpret_cast<const float2*>(
                                             eprow + n_base + nt * 8 + tig * 2));
                        ep[mt][nt][half * 2]     = v.x;
                        ep[mt][nt][half * 2 + 1] = v.y;
                    }
                }

            // ---- 3 chunks: k5..k7, bufs {3,4} cycled ----
            const int k5 = (cidx + 5) & 7, k6 = (cidx + 6) & 7, k7 = (cidx + 7) & 7;
            spin(k5); load_A(k5, 3);                 // c1
            spin(k6); load_A(k6, 4);                 // c2
            CP_WAIT(1); BAR_PAIR(pair_id);           // k5 joined
            PROC_CHUNK(3, k5);
            BAR_PAIR(pair_id);                       // buf3 free
            spin(k7); load_A(k7, 3);                 // c3
            CP_WAIT(1); BAR_PAIR(pair_id);           // k6 joined
            PROC_CHUNK(4, k6);
            CP_WAIT(0); BAR_PAIR(pair_id);           // k7 joined
            PROC_CHUNK(3, k7);

            BAR_G1();                                // all g1 reads of bufs 3-4 done

            // ---- stage partial acc + ep (fp16, overlays bufs 3-4) ----
            __half* stg = reinterpret_cast<__half*>(smem + STAGE_OFF);
#pragma unroll
            for (int mt = 0; mt < 2; mt++)
#pragma unroll
                for (int nt = 0; nt < 4; nt++) {
                    const int col_l = n_base + nt * 8 + tig * 2;
#pragma unroll
                    for (int half = 0; half < 2; half++) {
                        const int row_l = m_base + mt * 16 + lg + half * 8;
                        __half2 w;
                        w.x = __float2half(acc[mt][nt][half * 2 + 0]
                                           + ep[mt][nt][half * 2 + 0]);
                        w.y = __float2half(acc[mt][nt][half * 2 + 1]
                                           + ep[mt][nt][half * 2 + 1]);
                        *reinterpret_cast<__half2*>(
                            stg + row_l * STG_STRIDE + col_l) = w;
                    }
                }
            BAR_CTA();                               // #1: stage visible to g0
            BAR_CTA();                               // #2: g0 done; bufs reusable
        }
#undef PROC_CHUNK
    }
}

// ---------------- final logits ----------------
__global__ __launch_bounds__(256)
void final_logits_kernel(const float* __restrict__ Wout,
                         const float* __restrict__ bout,
                         float* __restrict__ out) {
    const __half* __restrict__ h = g_H[0];   // TLEN = 80 even -> plane 0
    int warp = threadIdx.x >> 5;
    int lane = threadIdx.x & 31;
    int row = blockIdx.x * 8 + warp;
    if (row >= BATCH) return;
    float s = 0.0f;
#pragma unroll
    for (int j = 0; j < UNITS / 32; j++) {
        int k = lane + j * 32;
        s += __half2float(h[(size_t)row * UNITS + k]) * Wout[k];
    }
#pragma unroll
    for (int o = 16; o; o >>= 1) s += __shfl_xor_sync(0xffffffff, s, o);
    if (lane == 0) out[row] = 1.0f / (1.0f + expf(-(s + bout[0])));
}

// ---------------- launch ----------------
extern "C" void kernel_launch(void* const* d_in, const int* in_sizes, int n_in,
                              void* d_out, int out_size) {
    const int*   inputs = (const int*)  d_in[0];
    const float* emb    = (const float*)d_in[1];
    const float* Wxh    = (const float*)d_in[2];
    const float* Whh    = (const float*)d_in[3];
    const float* bh     = (const float*)d_in[4];
    const float* Wout   = (const float*)d_in[5];
    const float* bout   = (const float*)d_in[6];
    float* out = (float*)d_out;

    cudaFuncSetAttribute(rnn_persistent,
                         cudaFuncAttributeMaxDynamicSharedMemorySize, SMEM_MAIN);
    cudaFuncSetAttribute(proj_gemm,
                         cudaFuncAttributeMaxDynamicSharedMemorySize, SMEM_PROJ);

    build_whh_kernel<<<(UNITS * UNITS + 255) / 256, 256>>>(Whh);
    build_wx_kernel<<<(UNITS * 128 + 255) / 256, 256>>>(Wxh);
    init_h_kernel<<<(BATCH * UNITS + 255) / 256, 256>>>();

    dim3 gp(UNITS / BN, (NWORDS + 127) / 128);   // (8, 274)
    proj_gemm<<<gp, 256, SMEM_PROJ>>>(emb, bh);

    rnn_persistent<<<NCTA, 256, SMEM_MAIN>>>(inputs);

    final_logits_kernel<<<BATCH / 8, 256>>>(Wout, bout, out);
}

// round 16
// speedup vs baseline: 1.1004x; 1.0122x over previous
#include <cuda_runtime.h>
#include <cuda_fp16.h>
#include <cstdint>
#include <math.h>

// ---------------- problem dims ----------------
#define BATCH 2048
#define TLEN  80
#define EDIM  100
#define NWORDS 35000
#define UNITS 512
#define KC    64               // K chunk (64 fp16 = 128 B row)
#define BM    64               // rows per CTA (2 CTAs/SM co-residency)
#define BN    64
#define NCTA  256              // 32 row-groups x 8 col CTAs
#define GRPSZ 8

// ---------------- static device scratch ----------------
__device__ __half g_H[2][BATCH * UNITS];          // hidden state, fp16
__device__ __half g_Whh_h[UNITS * UNITS];         // W_hh single fp16 plane, [n][k]
__device__ __half g_WX_h[UNITS * 128];            // W_xh single fp16 plane, [n][k pad 128]
__device__ __half g_embh[(size_t)NWORDS * 128];   // emb fp16, k padded to 128
__device__ float  g_EP[(size_t)NWORDS * UNITS];   // emb @ W_xh + b_h  (fp32)
__device__ unsigned g_flag[NCTA * 32];            // per (grp,col) flags, 128B stride

// ---------------- PTX helpers ----------------
__device__ __forceinline__ uint32_t smem_to_u32(const void* p) {
    uint32_t a;
    asm("{ .reg .u64 t; cvta.to.shared.u64 t, %1; cvt.u32.u64 %0, t; }" : "=r"(a) : "l"(p));
    return a;
}
__device__ __forceinline__ float tanh_fast(float x) {
    float r;
    asm("tanh.approx.f32 %0, %1;" : "=f"(r) : "f"(x));
    return r;
}
#define CP16(dst, src) \
    asm volatile("cp.async.cg.shared.global [%0], [%1], 16;" :: "r"(dst), "l"(src))
#define CP_COMMIT() asm volatile("cp.async.commit_group;" ::: "memory")
#define CP_WAIT(n)  asm volatile("cp.async.wait_group %0;" :: "n"(n) : "memory")

#define LDSM_X4(r0, r1, r2, r3, addr) \
    asm volatile("ldmatrix.sync.aligned.m8n8.x4.shared.b16 {%0,%1,%2,%3}, [%4];" \
                 : "=r"(r0), "=r"(r1), "=r"(r2), "=r"(r3) : "r"(addr))

#define MMAF16(d, a0, a1, a2, a3, b0, b1) \
    asm volatile("mma.sync.aligned.m16n8k16.row.col.f32.f16.f16.f32 " \
                 "{%0,%1,%2,%3}, {%4,%5,%6,%7}, {%8,%9}, {%0,%1,%2,%3};" \
                 : "+f"((d)[0]), "+f"((d)[1]), "+f"((d)[2]), "+f"((d)[3]) \
                 : "r"(a0), "r"(a1), "r"(a2), "r"(a3), "r"(b0), "r"(b1))

#define SWZ(bo) ((bo) ^ (((bo) >> 3) & 0x70))

#define BAR_CTA()    asm volatile("barrier.sync 0;" ::: "memory")
#define BAR_G1()     asm volatile("barrier.sync 1, 128;" ::: "memory")
#define BAR_PAIR(id) asm volatile("barrier.sync %0, 64;" :: "r"(id) : "memory")

// ---------------- SMEM layouts ----------------
// main: B resident 8 chunks x 8KB = 64KB; A 5 bufs x 8KB = 40KB (g0: 0-2, g1: 3-4)
// stage (g1 partial acc + ep, fp16, 64 x 72 = 9216B) overlays bufs 3-4 (after BAR_G1)
#define B_RES(c)     ((c) * 8192)
#define A_OFF(buf)   (65536 + (buf) * 8192)
#define STAGE_OFF    A_OFF(3)
#define STG_STRIDE   72                            // halves per row (144 B)
#define SMEM_MAIN    (65536 + 5 * 8192)            // 106496 -> 2 CTAs/SM
// proj: A fp16 2 chunks x 16KB = 32KB; B single plane 2 chunks x 8KB = 16KB
#define PA(ch)       ((ch) * 16384)
#define PB(ch)       (32768 + (ch) * 8192)
#define SMEM_PROJ    49152

// ---------------- prep kernels ----------------
__global__ void build_whh_kernel(const float* __restrict__ Whh) {
    int i = blockIdx.x * blockDim.x + threadIdx.x;
    if (i >= UNITS * UNITS) return;
    int n = i / UNITS;
    int k = i - n * UNITS;
    g_Whh_h[i] = __float2half(Whh[(size_t)k * UNITS + n]);
}

__global__ void build_wx_kernel(const float* __restrict__ Wxh) {
    int i = blockIdx.x * blockDim.x + threadIdx.x;
    if (i >= UNITS * 128) return;
    int n = i >> 7;
    int k = i & 127;
    float v = (k < EDIM) ? Wxh[(size_t)k * UNITS + n] : 0.0f;
    g_WX_h[i] = __float2half(v);
}

// emb fp32 [NWORDS][100] -> fp16 [NWORDS][128] (zero-padded)
__global__ void build_emb_kernel(const float* __restrict__ emb) {
    size_t i = (size_t)blockIdx.x * blockDim.x + threadIdx.x;
    if (i >= (size_t)NWORDS * 128) return;
    int k = (int)(i & 127);
    size_t r = i >> 7;
    float v = (k < EDIM) ? emb[r * EDIM + k] : 0.0f;
    g_embh[i] = __float2half(v);
}

__global__ void init_h_kernel() {
    int i = blockIdx.x * blockDim.x + threadIdx.x;
    if (i < NCTA * 32) g_flag[i] = 0u;
    if (i >= BATCH * UNITS) return;
    g_H[0][i] = __float2half(0.0f);
}

// ---------------- table projection: g_EP = g_embh @ W_xh + b_h ----------------
__global__ __launch_bounds__(256, 2)
void proj_gemm(const float* __restrict__ bh) {
    extern __shared__ char smem[];
    const uint32_t su = smem_to_u32(smem);
    const int tid = threadIdx.x, wid = tid >> 5, lane = tid & 31;
    const int col0 = blockIdx.x * BN;
    const int r0   = blockIdx.y * 128;

    // A tiles via cp.async: 128 rows x 2 chunks x 8 segs = 2048 16B units.
    // Rows >= NWORDS clamp to the last row (their outputs are never stored).
    {
#pragma unroll
        for (int i = 0; i < 8; i++) {
            int u = tid + i * 256;
            int ch = u >> 10;                 // 0..1
            int r  = (u >> 3) & 127;          // 0..127
            int s  = u & 7;
            int gr = r0 + r;
            if (gr >= NWORDS) gr = NWORDS - 1;
            uint32_t so = SWZ((uint32_t)(r * 128 + s * 16));
            const __half* src = g_embh + (size_t)gr * 128 + ch * 64;
            CP16(su + PA(ch) + so, (const char*)src + s * 16);
        }
    }
    // B plane via cp.async (1024 16B units)
    {
#pragma unroll
        for (int i = 0; i < 4; i++) {
            int u = tid + i * 256;
            int ch = u >> 9;
            int r  = (u >> 3) & 63;
            int s  = u & 7;
            uint32_t so = SWZ((uint32_t)(r * 128 + s * 16));
            const __half* wsrc = g_WX_h + (size_t)(col0 + r) * 128 + ch * 64;
            CP16(su + PB(ch) + so, (const char*)wsrc + s * 16);
        }
    }
    CP_COMMIT();
    CP_WAIT(0);
    __syncthreads();

    const int m_base = (wid & 3) * 32;
    const int n_base = (wid >> 2) * 32;
    const int a_row = lane & 15, a_kh = (lane >> 4) * 16;
    const int b_row = ((lane >> 4) << 3) + (lane & 7), b_kh = ((lane >> 3) & 1) * 16;
    const int lg = lane >> 2, tig = lane & 3;

    float acc[2][4][4];
#pragma unroll
    for (int mt = 0; mt < 2; mt++)
#pragma unroll
        for (int nt = 0; nt < 4; nt++)
#pragma unroll
            for (int q = 0; q < 4; q++) acc[mt][nt][q] = 0.0f;

#pragma unroll
    for (int ks = 0; ks < 7; ks++) {      // K eff = 112 (k in [100,112) zero)
        const int ch = ks >> 2;
        const int kb = (ks & 3) * 32;
        uint32_t A[2][4], Bh[4][2];
#pragma unroll
        for (int mt = 0; mt < 2; mt++) {
            uint32_t bo = SWZ((uint32_t)((m_base + mt * 16 + a_row) * 128 + kb + a_kh));
            LDSM_X4(A[mt][0], A[mt][1], A[mt][2], A[mt][3], su + PA(ch) + bo);
        }
#pragma unroll
        for (int np = 0; np < 2; np++) {
            uint32_t bo = SWZ((uint32_t)((n_base + np * 16 + b_row) * 128 + kb + b_kh));
            LDSM_X4(Bh[np * 2][0], Bh[np * 2][1], Bh[np * 2 + 1][0], Bh[np * 2 + 1][1],
                    su + PB(ch) + bo);
        }
#pragma unroll
        for (int mt = 0; mt < 2; mt++)
#pragma unroll
            for (int nt = 0; nt < 4; nt++)
                MMAF16(acc[mt][nt], A[mt][0], A[mt][1], A[mt][2], A[mt][3],
                       Bh[nt][0], Bh[nt][1]);
    }

#pragma unroll
    for (int mt = 0; mt < 2; mt++)
#pragma unroll
        for (int nt = 0; nt < 4; nt++) {
            const int col = col0 + n_base + nt * 8 + tig * 2;
            const float b0 = __ldg(bh + col);
            const float b1 = __ldg(bh + col + 1);
#pragma unroll
            for (int half = 0; half < 2; half++) {
                const int row = r0 + m_base + mt * 16 + lg + half * 8;
                if (row < NWORDS) {
                    float2 v;
                    v.x = acc[mt][nt][half * 2] + b0;
                    v.y = acc[mt][nt][half * 2 + 1] + b1;
                    *reinterpret_cast<float2*>(g_EP + (size_t)row * UNITS + col) = v;
                }
            }
        }
}

// ---------------- persistent recurrence: BM=64, 2 CTAs/SM, split-K 5/3 ----------------
__global__ __launch_bounds__(256, 2)
void rnn_persistent(const int* __restrict__ inputs) {
    extern __shared__ char smem[];
    const uint32_t su = smem_to_u32(smem);
    const int tid = threadIdx.x, wid = tid >> 5, lane = tid & 31;
    const int kg  = wid >> 2;                      // k-group 0/1 (4 warps each)
    const int wg  = wid & 3;
    const int bid = blockIdx.x;
    const int cidx = bid & 7;
    const int grp  = bid >> 3;                     // 0..31
    const int col0 = cidx * BN, row0 = grp * BM;

    // resident B: W_hh single plane, 8 chunks (64KB, 4096 16B units)
    {
#pragma unroll
        for (int i = 0; i < 16; i++) {
            int u = tid + i * 256;
            int rg = u >> 3, s = u & 7;
            int ch = rg >> 6, r = rg & 63;
            uint32_t so = SWZ((uint32_t)(r * 128 + s * 16));
            size_t gs = (size_t)(col0 + r) * UNITS + ch * 64;
            CP16(su + B_RES(ch) + so, (const char*)(g_Whh_h + gs) + s * 16);
        }
    }
    CP_COMMIT();
    // prefill A buffer 0 with zeros (H_0 own chunk, forwarded path): 8KB
    {
        uint4 z = make_uint4(0, 0, 0, 0);
        reinterpret_cast<uint4*>(smem + A_OFF(0))[tid]       = z;
        reinterpret_cast<uint4*>(smem + A_OFF(0))[tid + 256] = z;
    }
    CP_WAIT(0);
    __syncthreads();

    const int m_base = (wg & 1) * 32;
    const int n_base = (wg >> 1) * 32;
    const int mrow0  = m_base + (wg >> 1) * 16;    // this warp's 16-row load slice
    const int pair_id = 2 + kg * 2 + (wg & 1);     // named barrier per m-pair, ids 2..5
    const int a_row = lane & 15, a_kh = (lane >> 4) * 16;
    const int b_row = ((lane >> 4) << 3) + (lane & 7), b_kh = ((lane >> 3) & 1) * 16;
    const int lg = lane >> 2, tig = lane & 3;

    for (int t = 0; t < TLEN; t++) {
        const __half* __restrict__ Hsrc = g_H[t & 1];

        float acc[2][4][4];
#pragma unroll
        for (int mt = 0; mt < 2; mt++)
#pragma unroll
            for (int nt = 0; nt < 4; nt++)
#pragma unroll
                for (int q = 0; q < 4; q++) acc[mt][nt][q] = 0.0f;

        auto spin = [&](int kc) {
            const unsigned* fp = &g_flag[(grp * 8 + kc) * 32];
            unsigned v;
            do {
                asm volatile("ld.acquire.gpu.u32 %0, [%1];" : "=r"(v) : "l"(fp));
            } while ((int)v < t);
        };
        // pair-cooperative: this warp loads its 16 rows of chunk kc (2KB = 128 units)
        auto load_A = [&](int kc, int buf) {
            const __half* sh = Hsrc + (size_t)(row0 + mrow0) * UNITS + kc * KC;
#pragma unroll
            for (int i = 0; i < 4; i++) {
                int u = lane + i * 32;           // 0..127
                int r = u >> 3, s = u & 7;       // r 0..15
                uint32_t so = SWZ((uint32_t)((mrow0 + r) * 128 + s * 16));
                CP16(su + A_OFF(buf) + so, (const char*)(sh + (size_t)r * UNITS) + s * 16);
            }
            CP_COMMIT();
        };

#define PROC_CHUNK(abuf, kc) do {                                             \
            const uint32_t ah_ = su + A_OFF(abuf);                            \
            const uint32_t bh_ = su + B_RES(kc);                              \
            _Pragma("unroll")                                                 \
            for (int ks_ = 0; ks_ < 4; ks_++) {                               \
                const int kb_ = ks_ * 32;                                     \
                uint32_t Af_[2][4], Bh_[4][2];                                \
                _Pragma("unroll")                                             \
                for (int mt_ = 0; mt_ < 2; mt_++) {                           \
                    uint32_t bo = SWZ((uint32_t)((m_base + mt_ * 16 + a_row)  \
                                                 * 128 + kb_ + a_kh));        \
                    LDSM_X4(Af_[mt_][0], Af_[mt_][1], Af_[mt_][2],            \
                            Af_[mt_][3], ah_ + bo);                           \
                }                                                             \
                _Pragma("unroll")                                             \
                for (int np_ = 0; np_ < 2; np_++) {                           \
                    uint32_t bo = SWZ((uint32_t)((n_base + np_ * 16 + b_row)  \
                                                 * 128 + kb_ + b_kh));        \
                    LDSM_X4(Bh_[np_ * 2][0], Bh_[np_ * 2][1],                 \
                            Bh_[np_ * 2 + 1][0], Bh_[np_ * 2 + 1][1],         \
                            bh_ + bo);                                        \
                }                                                             \
                _Pragma("unroll")                                             \
                for (int mt_ = 0; mt_ < 2; mt_++)                             \
                    _Pragma("unroll")                                         \
                    for (int nt_ = 0; nt_ < 4; nt_++)                         \
                        MMAF16(acc[mt_][nt_], Af_[mt_][0], Af_[mt_][1],       \
                               Af_[mt_][2], Af_[mt_][3],                      \
                               Bh_[nt_][0], Bh_[nt_][1]);                     \
            }                                                                 \
        } while (0)

        if (kg == 0) {
            // ---- 5 chunks: cidx (forwarded, buf0) + k1..k4, bufs {1,2} cycled ----
            const int k1 = (cidx + 1) & 7, k2 = (cidx + 2) & 7;
            const int k3 = (cidx + 3) & 7, k4 = (cidx + 4) & 7;
            spin(k1); load_A(k1, 1);                 // commit 1
            spin(k2); load_A(k2, 2);                 // commit 2
            PROC_CHUNK(0, cidx);
            CP_WAIT(1); BAR_PAIR(pair_id);           // k1 halves joined
            PROC_CHUNK(1, k1);
            BAR_PAIR(pair_id);                       // pair done reading buf1
            spin(k3); load_A(k3, 1);                 // commit 3
            CP_WAIT(1); BAR_PAIR(pair_id);           // k2 joined
            PROC_CHUNK(2, k2);
            BAR_PAIR(pair_id);                       // pair done reading buf2
            spin(k4); load_A(k4, 2);                 // commit 4
            CP_WAIT(1); BAR_PAIR(pair_id);           // k3 joined
            PROC_CHUNK(1, k3);
            CP_WAIT(0); BAR_PAIR(pair_id);           // k4 joined
            PROC_CHUNK(2, k4);

            BAR_CTA();                               // #1: stage ready

            // ---- combine + tanh + store + forward ----
            __half* __restrict__ Hdst = g_H[(t + 1) & 1];
            const __half* stg = reinterpret_cast<const __half*>(smem + STAGE_OFF);
#pragma unroll
            for (int mt = 0; mt < 2; mt++)
#pragma unroll
                for (int nt = 0; nt < 4; nt++) {
                    const int col_l = n_base + nt * 8 + tig * 2;
                    const int col   = col0 + col_l;
#pragma unroll
                    for (int half = 0; half < 2; half++) {
                        const int row_l = m_base + mt * 16 + lg + half * 8;
                        __half2 s2 = *reinterpret_cast<const __half2*>(
                                         stg + row_l * STG_STRIDE + col_l);
                        float v0 = tanh_fast(acc[mt][nt][half * 2 + 0] + __half2float(s2.x));
                        float v1 = tanh_fast(acc[mt][nt][half * 2 + 1] + __half2float(s2.y));
                        __half2 hp;
                        hp.x = __float2half(v0);
                        hp.y = __float2half(v1);
                        *reinterpret_cast<__half2*>(
                            Hdst + (size_t)(row0 + row_l) * UNITS + col) = hp;
                        uint32_t so = SWZ((uint32_t)(row_l * 128 + col_l * 2));
                        *reinterpret_cast<__half2*>(smem + A_OFF(0) + so) = hp;
                    }
                }

            BAR_CTA();                               // #2: forwarding + stores visible
            if (tid == 0) {
                __threadfence();
                unsigned* fp = &g_flag[(grp * 8 + cidx) * 32];
                asm volatile("st.release.gpu.u32 [%0], %1;"
                             :: "l"(fp), "r"((unsigned)(t + 1)) : "memory");
            }
        } else {
            // ---- EP gather (xw + bias, fp32) — issued early, consumed at stage ----
            float ep[2][4][4];
#pragma unroll
            for (int mt = 0; mt < 2; mt++)
#pragma unroll
                for (int half = 0; half < 2; half++) {
                    const int row = row0 + m_base + mt * 16 + lg + half * 8;
                    const int idx = __ldg(inputs + (size_t)row * TLEN + t);
                    const float* eprow = g_EP + (size_t)idx * UNITS + col0;
#pragma unroll
                    for (int nt = 0; nt < 4; nt++) {
                        float2 v = __ldg(reinterpret_cast<const float2*>(
                                             eprow + n_base + nt * 8 + tig * 2));
                        ep[mt][nt][half * 2]     = v.x;
                        ep[mt][nt][half * 2 + 1] = v.y;
                    }
                }

            // ---- 3 chunks: k5..k7, bufs {3,4} cycled ----
            const int k5 = (cidx + 5) & 7, k6 = (cidx + 6) & 7, k7 = (cidx + 7) & 7;
            spin(k5); load_A(k5, 3);                 // c1
            spin(k6); load_A(k6, 4);                 // c2
            CP_WAIT(1); BAR_PAIR(pair_id);           // k5 joined
            PROC_CHUNK(3, k5);
            BAR_PAIR(pair_id);                       // buf3 free
            spin(k7); load_A(k7, 3);                 // c3
            CP_WAIT(1); BAR_PAIR(pair_id);           // k6 joined
            PROC_CHUNK(4, k6);
            CP_WAIT(0); BAR_PAIR(pair_id);           // k7 joined
            PROC_CHUNK(3, k7);

            BAR_G1();                                // all g1 reads of bufs 3-4 done

            // ---- stage partial acc + ep (fp16, overlays bufs 3-4) ----
            __half* stg = reinterpret_cast<__half*>(smem + STAGE_OFF);
#pragma unroll
            for (int mt = 0; mt < 2; mt++)
#pragma unroll
                for (int nt = 0; nt < 4; nt++) {
                    const int col_l = n_base + nt * 8 + tig * 2;
#pragma unroll
                    for (int half = 0; half < 2; half++) {
                        const int row_l = m_base + mt * 16 + lg + half * 8;
                        __half2 w;
                        w.x = __float2half(acc[mt][nt][half * 2 + 0]
                                           + ep[mt][nt][half * 2 + 0]);
                        w.y = __float2half(acc[mt][nt][half * 2 + 1]
                                           + ep[mt][nt][half * 2 + 1]);
                        *reinterpret_cast<__half2*>(
                            stg + row_l * STG_STRIDE + col_l) = w;
                    }
                }
            BAR_CTA();                               // #1: stage visible to g0
            BAR_CTA();                               // #2: g0 done; bufs reusable
        }
#undef PROC_CHUNK
    }
}

// ---------------- final logits ----------------
__global__ __launch_bounds__(256)
void final_logits_kernel(const float* __restrict__ Wout,
                         const float* __restrict__ bout,
                         float* __restrict__ out) {
    const __half* __restrict__ h = g_H[0];   // TLEN = 80 even -> plane 0
    int warp = threadIdx.x >> 5;
    int lane = threadIdx.x & 31;
    int row = blockIdx.x * 8 + warp;
    if (row >= BATCH) return;
    float s = 0.0f;
#pragma unroll
    for (int j = 0; j < UNITS / 32; j++) {
        int k = lane + j * 32;
        s += __half2float(h[(size_t)row * UNITS + k]) * Wout[k];
    }
#pragma unroll
    for (int o = 16; o; o >>= 1) s += __shfl_xor_sync(0xffffffff, s, o);
    if (lane == 0) out[row] = 1.0f / (1.0f + expf(-(s + bout[0])));
}

// ---------------- launch ----------------
extern "C" void kernel_launch(void* const* d_in, const int* in_sizes, int n_in,
                              void* d_out, int out_size) {
    const int*   inputs = (const int*)  d_in[0];
    const float* emb    = (const float*)d_in[1];
    const float* Wxh    = (const float*)d_in[2];
    const float* Whh    = (const float*)d_in[3];
    const float* bh     = (const float*)d_in[4];
    const float* Wout   = (const float*)d_in[5];
    const float* bout   = (const float*)d_in[6];
    float* out = (float*)d_out;

    cudaFuncSetAttribute(rnn_persistent,
                         cudaFuncAttributeMaxDynamicSharedMemorySize, SMEM_MAIN);
    cudaFuncSetAttribute(proj_gemm,
                         cudaFuncAttributeMaxDynamicSharedMemorySize, SMEM_PROJ);

    build_whh_kernel<<<(UNITS * UNITS + 255) / 256, 256>>>(Whh);
    build_wx_kernel<<<(UNITS * 128 + 255) / 256, 256>>>(Wxh);
    {
        size_t n = (size_t)NWORDS * 128;
        build_emb_kernel<<<(unsigned)((n + 255) / 256), 256>>>(emb);
    }
    init_h_kernel<<<(BATCH * UNITS + 255) / 256, 256>>>();

    dim3 gp(UNITS / BN, (NWORDS + 127) / 128);   // (8, 274)
    proj_gemm<<<gp, 256, SMEM_PROJ>>>(bh);

    rnn_persistent<<<NCTA, 256, SMEM_MAIN>>>(inputs);

    final_logits_kernel<<<BATCH / 8, 256>>>(Wout, bout, out);
}